// round 9
// baseline (speedup 1.0000x reference)
#include <cuda_runtime.h>
#include <cuda_bf16.h>
#include <cstdint>

#define NUM_HEADS 8
#define GS 7
#define NTOK 49
#define HDIM 32
#define CCH 256
#define NBIAS 169
#define HID 64
#define SCALE 0.17677669529663687f   // 32^-0.5
#define BJP 56                        // padded bias row length (floats)
#define STRB 80                       // smem row stride (bytes), conflict-free for ldmatrix
#define MATB (64 * STRB)              // bytes per 64-row bf16 matrix (5120)
#define BIASB (NTOK * BJP * 4)        // bias block bytes (10976)
#define SMEMB (8 * MATB + BIASB)      // 51936 (dynamic)

__device__ float g_biasP[NUM_HEADS * NTOK * BJP];

// ---------------- helpers ----------------
__device__ __forceinline__ uint32_t smem_u32(const void* p) {
    uint32_t a;
    asm("{ .reg .u64 t; cvta.to.shared.u64 t, %1; cvt.u32.u64 %0, t; }" : "=r"(a) : "l"(p));
    return a;
}
__device__ __forceinline__ void ldsm4(uint32_t* r, uint32_t a) {
    asm volatile("ldmatrix.sync.aligned.m8n8.x4.shared.b16 {%0,%1,%2,%3}, [%4];"
                 : "=r"(r[0]), "=r"(r[1]), "=r"(r[2]), "=r"(r[3]) : "r"(a));
}
__device__ __forceinline__ void ldsm4t(uint32_t* r, uint32_t a) {
    asm volatile("ldmatrix.sync.aligned.m8n8.x4.trans.shared.b16 {%0,%1,%2,%3}, [%4];"
                 : "=r"(r[0]), "=r"(r[1]), "=r"(r[2]), "=r"(r[3]) : "r"(a));
}
__device__ __forceinline__ void mma16816(float* c, const uint32_t* a, const uint32_t* b) {
    asm volatile("mma.sync.aligned.m16n8k16.row.col.f32.bf16.bf16.f32 "
                 "{%0,%1,%2,%3}, {%4,%5,%6,%7}, {%8,%9}, {%0,%1,%2,%3};"
                 : "+f"(c[0]), "+f"(c[1]), "+f"(c[2]), "+f"(c[3])
                 : "r"(a[0]), "r"(a[1]), "r"(a[2]), "r"(a[3]), "r"(b[0]), "r"(b[1]));
}
// pack (lo,hi) floats -> bf16x2 (lo in low half)
__device__ __forceinline__ uint32_t packbf(float lo, float hi) {
    uint32_t d;
    asm("cvt.rn.bf16x2.f32 %0, %1, %2;" : "=r"(d) : "f"(hi), "f"(lo));
    return d;
}
// split pair into bf16 hi part + bf16 residual part
__device__ __forceinline__ void split2(float e0, float e1, uint32_t& hi, uint32_t& lo) {
    hi = packbf(e0, e1);
    float h0 = __uint_as_float(hi << 16);
    float h1 = __uint_as_float(hi & 0xFFFF0000u);
    lo = packbf(e0 - h0, e1 - h1);
}

// ---------------- bias precompute: [h][i][j] padded to 56 cols ----------------
__global__ void bias_kernel(const float* __restrict__ W1, const float* __restrict__ b1,
                            const float* __restrict__ W2, const float* __restrict__ b2) {
    __shared__ float pos[NBIAS];
    const int h = blockIdx.x;
    const int t = threadIdx.x;
    if (t < NBIAS) {
        float bh = (float)(t / (2 * GS - 1)) - (float)(GS - 1);
        float bw = (float)(t % (2 * GS - 1)) - (float)(GS - 1);
        float acc = b2[h];
        for (int kk = 0; kk < HID; ++kk) {
            float hv = fmaxf(fmaf(bh, W1[kk], fmaf(bw, W1[HID + kk], b1[kk])), 0.0f);
            acc = fmaf(hv, W2[kk * NUM_HEADS + h], acc);
        }
        pos[t] = acc;
    }
    __syncthreads();
    for (int idx = t; idx < NTOK * BJP; idx += blockDim.x) {
        int i = idx / BJP;
        int j = idx % BJP;
        float val = 0.0f;
        if (j < NTOK) {
            int rel = (i / GS - j / GS + (GS - 1)) * (2 * GS - 1) + (i % GS - j % GS + (GS - 1));
            val = pos[rel];
        }
        g_biasP[(h * NTOK + i) * BJP + j] = val;
    }
}

// ------- mma attention: CTA = 2 windows (same head), 8 warps, shared bias -------
__global__ __launch_bounds__(256, 4)
void attn_mma(const float* __restrict__ q, const float* __restrict__ k,
              const float* __restrict__ v, float* __restrict__ out) {
    extern __shared__ unsigned char sm[];   // [2 windows][Khi|Klo|Vhi|Vlo] + bias
    const int tid = threadIdx.x;
    const int lane = tid & 31;
    const int wid = tid >> 5;

    // pairing: same head h, two consecutive batches
    const int h = blockIdx.x & 7;
    const int bp = blockIdx.x >> 3;
    const long long base0 = (long long)(bp * 2)     * (NTOK * CCH) + h * HDIM;
    const long long base1 = (long long)(bp * 2 + 1) * (NTOK * CCH) + h * HDIM;

    float* sB = (float*)(sm + 8 * MATB);

    // ---- stage bias block for this head into smem (float4, coalesced) ----
    {
        const float4* gb = (const float4*)(g_biasP + h * (NTOK * BJP));
        float4* db = (float4*)sB;
#pragma unroll
        for (int it = 0; it < 3; ++it) {
            int idx = tid + it * 256;            // 0..767
            if (idx < (NTOK * BJP) / 4) db[idx] = gb[idx];
        }
    }

    // ---- zero pad rows 49..63 of all 8 matrices (float4: 5 per row) ----
    {
        const float4 z4 = make_float4(0.f, 0.f, 0.f, 0.f);
#pragma unroll
        for (int it = 0; it < 3; ++it) {
            int idx = tid + it * 256;            // 0..767, need 600
            if (idx < 600) {
                int m = idx / 75, rem = idx % 75;          // m in [0,8)
                int row = 49 + rem / 5, c = rem % 5;
                *(float4*)(sm + m * MATB + row * STRB + c * 16) = z4;
            }
        }
    }

    // ---- stage K, V (rows 0..48) of both windows as bf16 hi/lo ----
    for (int fr = tid >> 3; fr < 196; fr += 32) {
        int w = fr / 98, rem = fr % 98;
        int mat = rem / 49;       // 0 = K, 1 = V
        int row = rem % 49;
        const float* src = mat ? v : k;
        long long base = w ? base1 : base0;
        int c = tid & 7;
        float4 x = ((const float4*)(src + base + (long long)row * CCH))[c];
        uint32_t h0, l0, h1, l1;
        split2(x.x, x.y, h0, l0);
        split2(x.z, x.w, h1, l1);
        unsigned char* dst = sm + w * (4 * MATB) + mat * 2 * MATB + row * STRB + c * 8;
        *(uint2*)dst = make_uint2(h0, h1);
        *(uint2*)(dst + MATB) = make_uint2(l0, l1);
    }
    __syncthreads();

    const int wwin = wid >> 2;                    // window within CTA
    const long long base = wwin ? base1 : base0;
    const uint32_t wsb = smem_u32(sm) + wwin * (4 * MATB);
    const int r0 = (wid & 3) * 16 + (lane >> 2);
    const int r1 = r0 + 8;
    const bool p0 = (r0 < NTOK), p1 = (r1 < NTOK);
    const float* q0 = q + base + (long long)r0 * CCH;
    const float* q1 = q + base + (long long)r1 * CCH;
    const int cb = 2 * (lane & 3);

    // ---- S = Qs.K^T : sacc[ntile(7)][4]; kk outer to keep only 8 Q-frag regs live ----
    float sacc[7][4];
#pragma unroll
    for (int nt = 0; nt < 7; ++nt)
#pragma unroll
        for (int e = 0; e < 4; ++e) sacc[nt][e] = 0.f;

    const uint32_t kAddrBase = wsb + ((lane & 7) + ((lane & 16) ? 8 : 0)) * STRB + ((lane & 8) ? 16 : 0);

#pragma unroll
    for (int kk = 0; kk < 2; ++kk) {
        uint32_t qh[4], ql[4];
        {
            const float2 z2 = make_float2(0.f, 0.f);
            int c = cb + 16 * kk;
            float2 x0 = p0 ? *(const float2*)(q0 + c)     : z2;
            float2 x1 = p1 ? *(const float2*)(q1 + c)     : z2;
            float2 x2 = p0 ? *(const float2*)(q0 + c + 8) : z2;
            float2 x3 = p1 ? *(const float2*)(q1 + c + 8) : z2;
            split2(x0.x * SCALE, x0.y * SCALE, qh[0], ql[0]);
            split2(x1.x * SCALE, x1.y * SCALE, qh[1], ql[1]);
            split2(x2.x * SCALE, x2.y * SCALE, qh[2], ql[2]);
            split2(x3.x * SCALE, x3.y * SCALE, qh[3], ql[3]);
        }
#pragma unroll
        for (int p = 0; p < 4; ++p) {
            uint32_t kh[4], kl[4];
            uint32_t a = kAddrBase + p * (16 * STRB) + kk * 32;
            ldsm4(kh, a);
            ldsm4(kl, a + MATB);
#pragma unroll
            for (int nl = 0; nl < 2; ++nl) {
                int nt = 2 * p + nl;
                if (nt < 7) {
                    mma16816(sacc[nt], qh, &kh[2 * nl]);
                    mma16816(sacc[nt], qh, &kl[2 * nl]);
                    mma16816(sacc[nt], ql, &kh[2 * nl]);
                }
            }
        }
    }

    // ---- bias (from smem) + exp softmax (in fragments), deferred normalization ----
    float inv[2];
#pragma unroll
    for (int hh = 0; hh < 2; ++hh) {
        int i = (wid & 3) * 16 + (lane >> 2) + hh * 8;
        bool vrow = (i < NTOK);
        const float* bp2 = sB + (vrow ? i : 0) * BJP + cb;
        float rsum = 0.f;
#pragma unroll
        for (int nt = 0; nt < 7; ++nt) {
            float2 bb = *(const float2*)(bp2 + 8 * nt);
            int j0 = 8 * nt + cb;
            float s0 = sacc[nt][2 * hh] + bb.x;
            float s1 = sacc[nt][2 * hh + 1] + bb.y;
            float e0 = (vrow && j0 < NTOK) ? __expf(s0) : 0.f;
            float e1 = (vrow && j0 + 1 < NTOK) ? __expf(s1) : 0.f;
            sacc[nt][2 * hh] = e0;
            sacc[nt][2 * hh + 1] = e1;
            rsum += e0 + e1;
        }
        rsum += __shfl_xor_sync(0xffffffffu, rsum, 1);
        rsum += __shfl_xor_sync(0xffffffffu, rsum, 2);
        inv[hh] = __fdividef(1.f, rsum);
    }

    // ---- O = P.V : oacc[ntile(4)][4] ----
    float oacc[4][4];
#pragma unroll
    for (int n = 0; n < 4; ++n)
#pragma unroll
        for (int e = 0; e < 4; ++e) oacc[n][e] = 0.f;

    const uint32_t vAddrBase = wsb + 2 * MATB + (lane & 15) * STRB + (lane & 16);

#pragma unroll
    for (int kc = 0; kc < 4; ++kc) {
        uint32_t vh[2][4], vl[2][4];
#pragma unroll
        for (int np = 0; np < 2; ++np) {
            uint32_t a = vAddrBase + kc * (16 * STRB) + np * 32;
            ldsm4t(vh[np], a);
            ldsm4t(vl[np], a + MATB);
        }
        uint32_t ah[4], al[4];
        split2(sacc[2 * kc][0], sacc[2 * kc][1], ah[0], al[0]);
        split2(sacc[2 * kc][2], sacc[2 * kc][3], ah[1], al[1]);
        if (kc < 3) {
            split2(sacc[2 * kc + 1][0], sacc[2 * kc + 1][1], ah[2], al[2]);
            split2(sacc[2 * kc + 1][2], sacc[2 * kc + 1][3], ah[3], al[3]);
        } else {
            ah[2] = ah[3] = al[2] = al[3] = 0u;   // keys 56-63 are pad
        }
#pragma unroll
        for (int n = 0; n < 4; ++n) {
            const uint32_t* bh = &vh[n >> 1][2 * (n & 1)];
            const uint32_t* bl = &vl[n >> 1][2 * (n & 1)];
            mma16816(oacc[n], ah, bh);
            mma16816(oacc[n], ah, bl);
            mma16816(oacc[n], al, bh);
        }
    }

    // ---- epilogue: normalize + store ----
#pragma unroll
    for (int hh = 0; hh < 2; ++hh) {
        int i = (wid & 3) * 16 + (lane >> 2) + hh * 8;
        if (i < NTOK) {
            float* op = out + base + (long long)i * CCH + cb;
            float iv = inv[hh];
#pragma unroll
            for (int n = 0; n < 4; ++n) {
                float2 val = make_float2(oacc[n][2 * hh] * iv,
                                         oacc[n][2 * hh + 1] * iv);
                *(float2*)(op + 8 * n) = val;
            }
        }
    }
}

extern "C" void kernel_launch(void* const* d_in, const int* in_sizes, int n_in,
                              void* d_out, int out_size) {
    const float* q  = (const float*)d_in[0];
    const float* k  = (const float*)d_in[1];
    const float* v  = (const float*)d_in[2];
    const float* W1 = (const float*)d_in[3];
    const float* b1 = (const float*)d_in[4];
    const float* W2 = (const float*)d_in[5];
    const float* b2 = (const float*)d_in[6];
    float* out = (float*)d_out;

    const int B = in_sizes[0] / (NTOK * CCH);   // 2048
    const int nwin = B * NUM_HEADS;             // 16384

    cudaFuncSetAttribute(attn_mma, cudaFuncAttributeMaxDynamicSharedMemorySize, SMEMB);

    bias_kernel<<<NUM_HEADS, 256>>>(W1, b1, W2, b2);
    attn_mma<<<nwin / 2, 256, SMEMB>>>(q, k, v, out);
}

// round 10
// speedup vs baseline: 1.2204x; 1.2204x over previous
#include <cuda_runtime.h>
#include <cuda_bf16.h>
#include <cstdint>

#define NUM_HEADS 8
#define GS 7
#define NTOK 49
#define HDIM 32
#define CCH 256
#define NBIAS 169
#define HID 64
#define SCALE 0.17677669529663687f   // 32^-0.5
#define BJP 56                        // padded bias row length (floats)
#define STRB 80                       // smem row stride (bytes), conflict-free for ldmatrix
#define MATB (64 * STRB)              // bytes per 64-row bf16 matrix (5120)
#define BIASB (NTOK * BJP * 4)        // bias block bytes (10976)

__device__ float g_biasP[NUM_HEADS * NTOK * BJP];

// ---------------- helpers ----------------
__device__ __forceinline__ uint32_t smem_u32(const void* p) {
    uint32_t a;
    asm("{ .reg .u64 t; cvta.to.shared.u64 t, %1; cvt.u32.u64 %0, t; }" : "=r"(a) : "l"(p));
    return a;
}
__device__ __forceinline__ void ldsm4(uint32_t* r, uint32_t a) {
    asm volatile("ldmatrix.sync.aligned.m8n8.x4.shared.b16 {%0,%1,%2,%3}, [%4];"
                 : "=r"(r[0]), "=r"(r[1]), "=r"(r[2]), "=r"(r[3]) : "r"(a));
}
__device__ __forceinline__ void ldsm4t(uint32_t* r, uint32_t a) {
    asm volatile("ldmatrix.sync.aligned.m8n8.x4.trans.shared.b16 {%0,%1,%2,%3}, [%4];"
                 : "=r"(r[0]), "=r"(r[1]), "=r"(r[2]), "=r"(r[3]) : "r"(a));
}
__device__ __forceinline__ void mma16816(float* c, const uint32_t* a, const uint32_t* b) {
    asm volatile("mma.sync.aligned.m16n8k16.row.col.f32.bf16.bf16.f32 "
                 "{%0,%1,%2,%3}, {%4,%5,%6,%7}, {%8,%9}, {%0,%1,%2,%3};"
                 : "+f"(c[0]), "+f"(c[1]), "+f"(c[2]), "+f"(c[3])
                 : "r"(a[0]), "r"(a[1]), "r"(a[2]), "r"(a[3]), "r"(b[0]), "r"(b[1]));
}
// pack (lo,hi) floats -> bf16x2 (lo in low half)
__device__ __forceinline__ uint32_t packbf(float lo, float hi) {
    uint32_t d;
    asm("cvt.rn.bf16x2.f32 %0, %1, %2;" : "=r"(d) : "f"(hi), "f"(lo));
    return d;
}
// split pair into bf16 hi part + bf16 residual part
__device__ __forceinline__ void split2(float e0, float e1, uint32_t& hi, uint32_t& lo) {
    hi = packbf(e0, e1);
    float h0 = __uint_as_float(hi << 16);
    float h1 = __uint_as_float(hi & 0xFFFF0000u);
    lo = packbf(e0 - h0, e1 - h1);
}

// ---------------- bias precompute: [h][i][j] padded to 56 cols ----------------
__global__ void bias_kernel(const float* __restrict__ W1, const float* __restrict__ b1,
                            const float* __restrict__ W2, const float* __restrict__ b2) {
    __shared__ float pos[NBIAS];
    const int h = blockIdx.x;
    const int t = threadIdx.x;
    if (t < NBIAS) {
        float bh = (float)(t / (2 * GS - 1)) - (float)(GS - 1);
        float bw = (float)(t % (2 * GS - 1)) - (float)(GS - 1);
        float acc = b2[h];
        for (int kk = 0; kk < HID; ++kk) {
            float hv = fmaxf(fmaf(bh, W1[kk], fmaf(bw, W1[HID + kk], b1[kk])), 0.0f);
            acc = fmaf(hv, W2[kk * NUM_HEADS + h], acc);
        }
        pos[t] = acc;
    }
    __syncthreads();
    for (int idx = t; idx < NTOK * BJP; idx += blockDim.x) {
        int i = idx / BJP;
        int j = idx % BJP;
        float val = 0.0f;
        if (j < NTOK) {
            int rel = (i / GS - j / GS + (GS - 1)) * (2 * GS - 1) + (i % GS - j % GS + (GS - 1));
            val = pos[rel];
        }
        g_biasP[(h * NTOK + i) * BJP + j] = val;
    }
}

// ---------------- mma attention: CTA = 1 window, 4 warps x 16 rows ----------------
__global__ __launch_bounds__(128, 7)
void attn_mma(const float* __restrict__ q, const float* __restrict__ k,
              const float* __restrict__ v, float* __restrict__ out) {
    // smem: Khi | Klo | Vhi | Vlo (20480) + bias block (10976)
    __shared__ unsigned char sm[4 * MATB + BIASB];
    const int tid = threadIdx.x;
    const int lane = tid & 31;
    const int wid = tid >> 5;

    const int gwid = blockIdx.x;                 // window id = (b,h)
    const int h = gwid & 7;
    const long long base = (long long)(gwid >> 3) * (NTOK * CCH) + h * HDIM;

    float* sB = (float*)(sm + 4 * MATB);

    // ---- stage bias block for this head into smem (float4, fully unrolled) ----
    {
        const float4* gb = (const float4*)(g_biasP + h * (NTOK * BJP));
        float4* db = (float4*)sB;
#pragma unroll
        for (int it = 0; it < 6; ++it) {
            int idx = tid + it * 128;            // 0..685
            if (idx < (NTOK * BJP) / 4) db[idx] = gb[idx];
        }
    }

    // ---- zero pad rows 49..63 of V planes only (K pad is predicate-masked later) ----
    {
        const float4 z4 = make_float4(0.f, 0.f, 0.f, 0.f);
#pragma unroll
        for (int it = 0; it < 2; ++it) {
            int idx = tid + it * 128;            // need 150
            if (idx < 150) {
                int m = 2 + idx / 75, rem = idx % 75;
                int row = 49 + rem / 5, c = rem % 5;
                *(float4*)(sm + m * MATB + row * STRB + c * 16) = z4;
            }
        }
    }

    // ---- stage K, V (rows 0..48) as bf16 hi/lo — fully unrolled, LDGs batched ----
    {
        const int c = tid & 7;
        const int r0w = tid >> 3;                // 0..15
#pragma unroll
        for (int it = 0; it < 7; ++it) {
            int row = r0w + it * 16;             // 0..111
            if (row < 98) {
                int mat = (row >= 49) ? 1 : 0;   // 0 = K, 1 = V
                int r = row - 49 * mat;
                const float* src = mat ? v : k;
                float4 x = ((const float4*)(src + base + (long long)r * CCH))[c];
                uint32_t h0, l0, h1, l1;
                split2(x.x, x.y, h0, l0);
                split2(x.z, x.w, h1, l1);
                unsigned char* dst = sm + mat * 2 * MATB + r * STRB + c * 8;
                *(uint2*)dst = make_uint2(h0, h1);
                *(uint2*)(dst + MATB) = make_uint2(l0, l1);
            }
        }
    }
    __syncthreads();

    const uint32_t wsb = smem_u32(sm);
    const int r0 = wid * 16 + (lane >> 2);
    const int r1 = r0 + 8;
    const bool p0 = (r0 < NTOK), p1 = (r1 < NTOK);
    const float* q0 = q + base + (long long)r0 * CCH;
    const float* q1 = q + base + (long long)r1 * CCH;
    const int cb = 2 * (lane & 3);

    // ---- S = Qs.K^T : sacc[ntile(7)][4]; kk outer to keep only 8 Q-frag regs live ----
    float sacc[7][4];
#pragma unroll
    for (int nt = 0; nt < 7; ++nt)
#pragma unroll
        for (int e = 0; e < 4; ++e) sacc[nt][e] = 0.f;

    const uint32_t kAddrBase = wsb + ((lane & 7) + ((lane & 16) ? 8 : 0)) * STRB + ((lane & 8) ? 16 : 0);

#pragma unroll
    for (int kk = 0; kk < 2; ++kk) {
        // Q fragments for this 16-wide k-slice, straight from gmem (predicated)
        uint32_t qh[4], ql[4];
        {
            const float2 z2 = make_float2(0.f, 0.f);
            int c = cb + 16 * kk;
            float2 x0 = p0 ? *(const float2*)(q0 + c)     : z2;
            float2 x1 = p1 ? *(const float2*)(q1 + c)     : z2;
            float2 x2 = p0 ? *(const float2*)(q0 + c + 8) : z2;
            float2 x3 = p1 ? *(const float2*)(q1 + c + 8) : z2;
            split2(x0.x * SCALE, x0.y * SCALE, qh[0], ql[0]);
            split2(x1.x * SCALE, x1.y * SCALE, qh[1], ql[1]);
            split2(x2.x * SCALE, x2.y * SCALE, qh[2], ql[2]);
            split2(x3.x * SCALE, x3.y * SCALE, qh[3], ql[3]);
        }
#pragma unroll
        for (int p = 0; p < 4; ++p) {
            uint32_t kh[4], kl[4];
            uint32_t a = kAddrBase + p * (16 * STRB) + kk * 32;
            ldsm4(kh, a);
            ldsm4(kl, a + MATB);
#pragma unroll
            for (int nl = 0; nl < 2; ++nl) {
                int nt = 2 * p + nl;
                if (nt < 7) {
                    mma16816(sacc[nt], qh, &kh[2 * nl]);
                    mma16816(sacc[nt], qh, &kl[2 * nl]);
                    mma16816(sacc[nt], ql, &kh[2 * nl]);
                }
            }
        }
    }

    // ---- bias (from smem) + exp softmax (in fragments), deferred normalization ----
    float inv[2];
#pragma unroll
    for (int hh = 0; hh < 2; ++hh) {
        int i = wid * 16 + (lane >> 2) + hh * 8;
        bool vrow = (i < NTOK);
        const float* bp = sB + (vrow ? i : 0) * BJP + cb;
        float rsum = 0.f;
#pragma unroll
        for (int nt = 0; nt < 7; ++nt) {
            float2 bb = *(const float2*)(bp + 8 * nt);
            int j0 = 8 * nt + cb;
            float s0 = sacc[nt][2 * hh] + bb.x;
            float s1 = sacc[nt][2 * hh + 1] + bb.y;
            float e0 = (vrow && j0 < NTOK) ? __expf(s0) : 0.f;
            float e1 = (vrow && j0 + 1 < NTOK) ? __expf(s1) : 0.f;
            sacc[nt][2 * hh] = e0;
            sacc[nt][2 * hh + 1] = e1;
            rsum += e0 + e1;
        }
        rsum += __shfl_xor_sync(0xffffffffu, rsum, 1);
        rsum += __shfl_xor_sync(0xffffffffu, rsum, 2);
        inv[hh] = __fdividef(1.f, rsum);
    }

    // ---- O = P.V : oacc[ntile(4)][4] ----
    float oacc[4][4];
#pragma unroll
    for (int n = 0; n < 4; ++n)
#pragma unroll
        for (int e = 0; e < 4; ++e) oacc[n][e] = 0.f;

    const uint32_t vAddrBase = wsb + 2 * MATB + (lane & 15) * STRB + (lane & 16);

#pragma unroll
    for (int kc = 0; kc < 4; ++kc) {
        uint32_t vh[2][4], vl[2][4];
#pragma unroll
        for (int np = 0; np < 2; ++np) {
            uint32_t a = vAddrBase + kc * (16 * STRB) + np * 32;
            ldsm4t(vh[np], a);
            ldsm4t(vl[np], a + MATB);
        }
        uint32_t ah[4], al[4];
        split2(sacc[2 * kc][0], sacc[2 * kc][1], ah[0], al[0]);
        split2(sacc[2 * kc][2], sacc[2 * kc][3], ah[1], al[1]);
        if (kc < 3) {
            split2(sacc[2 * kc + 1][0], sacc[2 * kc + 1][1], ah[2], al[2]);
            split2(sacc[2 * kc + 1][2], sacc[2 * kc + 1][3], ah[3], al[3]);
        } else {
            ah[2] = ah[3] = al[2] = al[3] = 0u;   // keys 56-63 are pad
        }
#pragma unroll
        for (int n = 0; n < 4; ++n) {
            const uint32_t* bh = &vh[n >> 1][2 * (n & 1)];
            const uint32_t* bl = &vl[n >> 1][2 * (n & 1)];
            mma16816(oacc[n], ah, bh);
            mma16816(oacc[n], ah, bl);
            mma16816(oacc[n], al, bh);
        }
    }

    // ---- epilogue: normalize + store ----
#pragma unroll
    for (int hh = 0; hh < 2; ++hh) {
        int i = wid * 16 + (lane >> 2) + hh * 8;
        if (i < NTOK) {
            float* op = out + base + (long long)i * CCH + cb;
            float iv = inv[hh];
#pragma unroll
            for (int n = 0; n < 4; ++n) {
                float2 val = make_float2(oacc[n][2 * hh] * iv,
                                         oacc[n][2 * hh + 1] * iv);
                *(float2*)(op + 8 * n) = val;
            }
        }
    }
}

extern "C" void kernel_launch(void* const* d_in, const int* in_sizes, int n_in,
                              void* d_out, int out_size) {
    const float* q  = (const float*)d_in[0];
    const float* k  = (const float*)d_in[1];
    const float* v  = (const float*)d_in[2];
    const float* W1 = (const float*)d_in[3];
    const float* b1 = (const float*)d_in[4];
    const float* W2 = (const float*)d_in[5];
    const float* b2 = (const float*)d_in[6];
    float* out = (float*)d_out;

    const int B = in_sizes[0] / (NTOK * CCH);   // 2048
    const int nwin = B * NUM_HEADS;             // 16384

    bias_kernel<<<NUM_HEADS, 256>>>(W1, b1, W2, b2);
    attn_mma<<<nwin, 128>>>(q, k, v, out);
}

// round 11
// speedup vs baseline: 1.2776x; 1.0468x over previous
#include <cuda_runtime.h>
#include <cuda_fp16.h>
#include <cstdint>

#define NUM_HEADS 8
#define GS 7
#define NTOK 49
#define HDIM 32
#define CCH 256
#define NBIAS 169
#define HID 64
#define SCALE 0.17677669529663687f   // 32^-0.5
#define BJP 56                        // padded bias row length (halfs)
#define STRB 80                       // smem row stride (bytes), conflict-free for ldmatrix
#define MATB (64 * STRB)              // bytes per 64-row bf16 matrix (5120)
#define BIASB (NTOK * BJP * 2)        // bias block bytes, fp16 (5488)

__device__ __half g_biasH[NUM_HEADS * NTOK * BJP];

// ---------------- helpers ----------------
__device__ __forceinline__ uint32_t smem_u32(const void* p) {
    uint32_t a;
    asm("{ .reg .u64 t; cvta.to.shared.u64 t, %1; cvt.u32.u64 %0, t; }" : "=r"(a) : "l"(p));
    return a;
}
__device__ __forceinline__ void ldsm4(uint32_t* r, uint32_t a) {
    asm volatile("ldmatrix.sync.aligned.m8n8.x4.shared.b16 {%0,%1,%2,%3}, [%4];"
                 : "=r"(r[0]), "=r"(r[1]), "=r"(r[2]), "=r"(r[3]) : "r"(a));
}
__device__ __forceinline__ void ldsm4t(uint32_t* r, uint32_t a) {
    asm volatile("ldmatrix.sync.aligned.m8n8.x4.trans.shared.b16 {%0,%1,%2,%3}, [%4];"
                 : "=r"(r[0]), "=r"(r[1]), "=r"(r[2]), "=r"(r[3]) : "r"(a));
}
__device__ __forceinline__ void mma16816(float* c, const uint32_t* a, const uint32_t* b) {
    asm volatile("mma.sync.aligned.m16n8k16.row.col.f32.bf16.bf16.f32 "
                 "{%0,%1,%2,%3}, {%4,%5,%6,%7}, {%8,%9}, {%0,%1,%2,%3};"
                 : "+f"(c[0]), "+f"(c[1]), "+f"(c[2]), "+f"(c[3])
                 : "r"(a[0]), "r"(a[1]), "r"(a[2]), "r"(a[3]), "r"(b[0]), "r"(b[1]));
}
// pack (lo,hi) floats -> bf16x2 (lo in low half)
__device__ __forceinline__ uint32_t packbf(float lo, float hi) {
    uint32_t d;
    asm("cvt.rn.bf16x2.f32 %0, %1, %2;" : "=r"(d) : "f"(hi), "f"(lo));
    return d;
}
// split pair into bf16 hi part + bf16 residual part
__device__ __forceinline__ void split2(float e0, float e1, uint32_t& hi, uint32_t& lo) {
    hi = packbf(e0, e1);
    float h0 = __uint_as_float(hi << 16);
    float h1 = __uint_as_float(hi & 0xFFFF0000u);
    lo = packbf(e0 - h0, e1 - h1);
}

// ---------------- bias precompute: [h][i][j] fp16, padded to 56 cols ----------------
__global__ void bias_kernel(const float* __restrict__ W1, const float* __restrict__ b1,
                            const float* __restrict__ W2, const float* __restrict__ b2) {
    __shared__ float pos[NBIAS];
    const int h = blockIdx.x;
    const int t = threadIdx.x;
    if (t < NBIAS) {
        float bh = (float)(t / (2 * GS - 1)) - (float)(GS - 1);
        float bw = (float)(t % (2 * GS - 1)) - (float)(GS - 1);
        float acc = b2[h];
        for (int kk = 0; kk < HID; ++kk) {
            float hv = fmaxf(fmaf(bh, W1[kk], fmaf(bw, W1[HID + kk], b1[kk])), 0.0f);
            acc = fmaf(hv, W2[kk * NUM_HEADS + h], acc);
        }
        pos[t] = acc;
    }
    __syncthreads();
    for (int idx = t; idx < NTOK * BJP; idx += blockDim.x) {
        int i = idx / BJP;
        int j = idx % BJP;
        float val = 0.0f;
        if (j < NTOK) {
            int rel = (i / GS - j / GS + (GS - 1)) * (2 * GS - 1) + (i % GS - j % GS + (GS - 1));
            val = pos[rel];
        }
        g_biasH[(h * NTOK + i) * BJP + j] = __float2half(val);
    }
}

// ---------------- mma attention: CTA = 1 window, 4 warps x 16 rows ----------------
__global__ __launch_bounds__(128, 8)
void attn_mma(const float* __restrict__ q, const float* __restrict__ k,
              const float* __restrict__ v, float* __restrict__ out) {
    // smem: Khi | Klo | Vhi | Vlo (20480) + fp16 bias block (5488)
    __shared__ unsigned char sm[4 * MATB + BIASB];
    const int tid = threadIdx.x;
    const int lane = tid & 31;
    const int wid = tid >> 5;

    const int gwid = blockIdx.x;                 // window id = (b,h)
    const int h = gwid & 7;
    const long long base = (long long)(gwid >> 3) * (NTOK * CCH) + h * HDIM;

    __half* sB = (__half*)(sm + 4 * MATB);

    // ---- stage fp16 bias block for this head into smem (uint4, unrolled) ----
    {
        const uint4* gb = (const uint4*)(g_biasH + h * (NTOK * BJP));
        uint4* db = (uint4*)sB;
#pragma unroll
        for (int it = 0; it < 3; ++it) {
            int idx = tid + it * 128;            // 0..342
            if (idx < BIASB / 16) db[idx] = gb[idx];
        }
    }

    // ---- zero pad rows 49..63 of V planes only (K pad is predicate-masked later) ----
    {
        const float4 z4 = make_float4(0.f, 0.f, 0.f, 0.f);
#pragma unroll
        for (int it = 0; it < 2; ++it) {
            int idx = tid + it * 128;            // need 150
            if (idx < 150) {
                int m = 2 + idx / 75, rem = idx % 75;
                int row = 49 + rem / 5, c = rem % 5;
                *(float4*)(sm + m * MATB + row * STRB + c * 16) = z4;
            }
        }
    }

    // ---- stage K, V (rows 0..48) as bf16 hi/lo — fully unrolled, LDGs batched ----
    {
        const int c = tid & 7;
        const int r0w = tid >> 3;                // 0..15
#pragma unroll
        for (int it = 0; it < 7; ++it) {
            int row = r0w + it * 16;             // 0..111
            if (row < 98) {
                int mat = (row >= 49) ? 1 : 0;   // 0 = K, 1 = V
                int r = row - 49 * mat;
                const float* src = mat ? v : k;
                float4 x = ((const float4*)(src + base + (long long)r * CCH))[c];
                uint32_t h0, l0, h1, l1;
                split2(x.x, x.y, h0, l0);
                split2(x.z, x.w, h1, l1);
                unsigned char* dst = sm + mat * 2 * MATB + r * STRB + c * 8;
                *(uint2*)dst = make_uint2(h0, h1);
                *(uint2*)(dst + MATB) = make_uint2(l0, l1);
            }
        }
    }
    __syncthreads();

    const uint32_t wsb = smem_u32(sm);
    const int r0 = wid * 16 + (lane >> 2);
    const int r1 = r0 + 8;
    const bool p0 = (r0 < NTOK), p1 = (r1 < NTOK);
    const float* q0 = q + base + (long long)r0 * CCH;
    const float* q1 = q + base + (long long)r1 * CCH;
    const int cb = 2 * (lane & 3);

    // ---- S = Qs.K^T : sacc[ntile(7)][4]; kk outer to keep only 8 Q-frag regs live ----
    float sacc[7][4];
#pragma unroll
    for (int nt = 0; nt < 7; ++nt)
#pragma unroll
        for (int e = 0; e < 4; ++e) sacc[nt][e] = 0.f;

    const uint32_t kAddrBase = wsb + ((lane & 7) + ((lane & 16) ? 8 : 0)) * STRB + ((lane & 8) ? 16 : 0);

#pragma unroll
    for (int kk = 0; kk < 2; ++kk) {
        // Q fragments for this 16-wide k-slice, straight from gmem (predicated)
        uint32_t qh[4], ql[4];
        {
            const float2 z2 = make_float2(0.f, 0.f);
            int c = cb + 16 * kk;
            float2 x0 = p0 ? *(const float2*)(q0 + c)     : z2;
            float2 x1 = p1 ? *(const float2*)(q1 + c)     : z2;
            float2 x2 = p0 ? *(const float2*)(q0 + c + 8) : z2;
            float2 x3 = p1 ? *(const float2*)(q1 + c + 8) : z2;
            split2(x0.x * SCALE, x0.y * SCALE, qh[0], ql[0]);
            split2(x1.x * SCALE, x1.y * SCALE, qh[1], ql[1]);
            split2(x2.x * SCALE, x2.y * SCALE, qh[2], ql[2]);
            split2(x3.x * SCALE, x3.y * SCALE, qh[3], ql[3]);
        }
#pragma unroll
        for (int p = 0; p < 4; ++p) {
            uint32_t kh[4], kl[4];
            uint32_t a = kAddrBase + p * (16 * STRB) + kk * 32;
            ldsm4(kh, a);
            ldsm4(kl, a + MATB);
#pragma unroll
            for (int nl = 0; nl < 2; ++nl) {
                int nt = 2 * p + nl;
                if (nt < 7) {
                    mma16816(sacc[nt], qh, &kh[2 * nl]);
                    mma16816(sacc[nt], qh, &kl[2 * nl]);
                    mma16816(sacc[nt], ql, &kh[2 * nl]);
                }
            }
        }
    }

    // ---- fp16 bias (from smem) + exp softmax (in fragments), deferred normalization ----
    float inv[2];
#pragma unroll
    for (int hh = 0; hh < 2; ++hh) {
        int i = wid * 16 + (lane >> 2) + hh * 8;
        bool vrow = (i < NTOK);
        const __half* bp = sB + (vrow ? i : 0) * BJP + cb;
        float rsum = 0.f;
#pragma unroll
        for (int nt = 0; nt < 7; ++nt) {
            float2 bb = __half22float2(*(const __half2*)(bp + 8 * nt));
            int j0 = 8 * nt + cb;
            float s0 = sacc[nt][2 * hh] + bb.x;
            float s1 = sacc[nt][2 * hh + 1] + bb.y;
            float e0 = (vrow && j0 < NTOK) ? __expf(s0) : 0.f;
            float e1 = (vrow && j0 + 1 < NTOK) ? __expf(s1) : 0.f;
            sacc[nt][2 * hh] = e0;
            sacc[nt][2 * hh + 1] = e1;
            rsum += e0 + e1;
        }
        rsum += __shfl_xor_sync(0xffffffffu, rsum, 1);
        rsum += __shfl_xor_sync(0xffffffffu, rsum, 2);
        inv[hh] = __fdividef(1.f, rsum);
    }

    // ---- O = P.V : oacc[ntile(4)][4] ----
    float oacc[4][4];
#pragma unroll
    for (int n = 0; n < 4; ++n)
#pragma unroll
        for (int e = 0; e < 4; ++e) oacc[n][e] = 0.f;

    const uint32_t vAddrBase = wsb + 2 * MATB + (lane & 15) * STRB + (lane & 16);

#pragma unroll
    for (int kc = 0; kc < 4; ++kc) {
        uint32_t vh[2][4], vl[2][4];
#pragma unroll
        for (int np = 0; np < 2; ++np) {
            uint32_t a = vAddrBase + kc * (16 * STRB) + np * 32;
            ldsm4t(vh[np], a);
            ldsm4t(vl[np], a + MATB);
        }
        uint32_t ah[4], al[4];
        split2(sacc[2 * kc][0], sacc[2 * kc][1], ah[0], al[0]);
        split2(sacc[2 * kc][2], sacc[2 * kc][3], ah[1], al[1]);
        if (kc < 3) {
            split2(sacc[2 * kc + 1][0], sacc[2 * kc + 1][1], ah[2], al[2]);
            split2(sacc[2 * kc + 1][2], sacc[2 * kc + 1][3], ah[3], al[3]);
        } else {
            ah[2] = ah[3] = al[2] = al[3] = 0u;   // keys 56-63 are pad
        }
#pragma unroll
        for (int n = 0; n < 4; ++n) {
            const uint32_t* bh = &vh[n >> 1][2 * (n & 1)];
            const uint32_t* bl = &vl[n >> 1][2 * (n & 1)];
            mma16816(oacc[n], ah, bh);
            mma16816(oacc[n], ah, bl);
            mma16816(oacc[n], al, bh);
        }
    }

    // ---- epilogue: normalize + store ----
#pragma unroll
    for (int hh = 0; hh < 2; ++hh) {
        int i = wid * 16 + (lane >> 2) + hh * 8;
        if (i < NTOK) {
            float* op = out + base + (long long)i * CCH + cb;
            float iv = inv[hh];
#pragma unroll
            for (int n = 0; n < 4; ++n) {
                float2 val = make_float2(oacc[n][2 * hh] * iv,
                                         oacc[n][2 * hh + 1] * iv);
                *(float2*)(op + 8 * n) = val;
            }
        }
    }
}

extern "C" void kernel_launch(void* const* d_in, const int* in_sizes, int n_in,
                              void* d_out, int out_size) {
    const float* q  = (const float*)d_in[0];
    const float* k  = (const float*)d_in[1];
    const float* v  = (const float*)d_in[2];
    const float* W1 = (const float*)d_in[3];
    const float* b1 = (const float*)d_in[4];
    const float* W2 = (const float*)d_in[5];
    const float* b2 = (const float*)d_in[6];
    float* out = (float*)d_out;

    const int B = in_sizes[0] / (NTOK * CCH);   // 2048
    const int nwin = B * NUM_HEADS;             // 16384

    bias_kernel<<<NUM_HEADS, 256>>>(W1, b1, W2, b2);
    attn_mma<<<nwin, 128>>>(q, k, v, out);
}

// round 12
// speedup vs baseline: 1.5198x; 1.1896x over previous
#include <cuda_runtime.h>
#include <cuda_fp16.h>
#include <cstdint>

#define NUM_HEADS 8
#define GS 7
#define NTOK 49
#define HDIM 32
#define CCH 256
#define NBIAS 169
#define HID 64
#define SCALE 0.17677669529663687f   // 32^-0.5
#define BJP 56                        // padded bias row length (halfs)
#define STRB 80                       // smem row stride (bytes), conflict-free for ldmatrix
#define MATB (64 * STRB)              // bytes per 64-row 16-bit matrix (5120)
#define BIASB (NTOK * BJP * 2)        // bias block bytes, fp16 (5488)

__device__ __half g_biasH[NUM_HEADS * NTOK * BJP];

// ---------------- helpers ----------------
__device__ __forceinline__ uint32_t smem_u32(const void* p) {
    uint32_t a;
    asm("{ .reg .u64 t; cvta.to.shared.u64 t, %1; cvt.u32.u64 %0, t; }" : "=r"(a) : "l"(p));
    return a;
}
__device__ __forceinline__ void ldsm4(uint32_t* r, uint32_t a) {
    asm volatile("ldmatrix.sync.aligned.m8n8.x4.shared.b16 {%0,%1,%2,%3}, [%4];"
                 : "=r"(r[0]), "=r"(r[1]), "=r"(r[2]), "=r"(r[3]) : "r"(a));
}
__device__ __forceinline__ void ldsm4t(uint32_t* r, uint32_t a) {
    asm volatile("ldmatrix.sync.aligned.m8n8.x4.trans.shared.b16 {%0,%1,%2,%3}, [%4];"
                 : "=r"(r[0]), "=r"(r[1]), "=r"(r[2]), "=r"(r[3]) : "r"(a));
}
__device__ __forceinline__ void mma16816(float* c, const uint32_t* a, const uint32_t* b) {
    asm volatile("mma.sync.aligned.m16n8k16.row.col.f32.bf16.bf16.f32 "
                 "{%0,%1,%2,%3}, {%4,%5,%6,%7}, {%8,%9}, {%0,%1,%2,%3};"
                 : "+f"(c[0]), "+f"(c[1]), "+f"(c[2]), "+f"(c[3])
                 : "r"(a[0]), "r"(a[1]), "r"(a[2]), "r"(a[3]), "r"(b[0]), "r"(b[1]));
}
__device__ __forceinline__ void mma16816h(float* c, const uint32_t* a, const uint32_t* b) {
    asm volatile("mma.sync.aligned.m16n8k16.row.col.f32.f16.f16.f32 "
                 "{%0,%1,%2,%3}, {%4,%5,%6,%7}, {%8,%9}, {%0,%1,%2,%3};"
                 : "+f"(c[0]), "+f"(c[1]), "+f"(c[2]), "+f"(c[3])
                 : "r"(a[0]), "r"(a[1]), "r"(a[2]), "r"(a[3]), "r"(b[0]), "r"(b[1]));
}
// pack (lo,hi) floats -> bf16x2 (lo in low half)
__device__ __forceinline__ uint32_t packbf(float lo, float hi) {
    uint32_t d;
    asm("cvt.rn.bf16x2.f32 %0, %1, %2;" : "=r"(d) : "f"(hi), "f"(lo));
    return d;
}
// pack (lo,hi) floats -> f16x2 (lo in low half)
__device__ __forceinline__ uint32_t packh2(float lo, float hi) {
    uint32_t d;
    asm("cvt.rn.f16x2.f32 %0, %1, %2;" : "=r"(d) : "f"(hi), "f"(lo));
    return d;
}
// split pair into bf16 hi part + bf16 residual part
__device__ __forceinline__ void split2(float e0, float e1, uint32_t& hi, uint32_t& lo) {
    hi = packbf(e0, e1);
    float h0 = __uint_as_float(hi << 16);
    float h1 = __uint_as_float(hi & 0xFFFF0000u);
    lo = packbf(e0 - h0, e1 - h1);
}

// ---------------- bias precompute: [h][i][j] fp16, padded to 56 cols ----------------
__global__ void bias_kernel(const float* __restrict__ W1, const float* __restrict__ b1,
                            const float* __restrict__ W2, const float* __restrict__ b2) {
    __shared__ float pos[NBIAS];
    const int h = blockIdx.x;
    const int t = threadIdx.x;
    if (t < NBIAS) {
        float bh = (float)(t / (2 * GS - 1)) - (float)(GS - 1);
        float bw = (float)(t % (2 * GS - 1)) - (float)(GS - 1);
        float acc = b2[h];
        for (int kk = 0; kk < HID; ++kk) {
            float hv = fmaxf(fmaf(bh, W1[kk], fmaf(bw, W1[HID + kk], b1[kk])), 0.0f);
            acc = fmaf(hv, W2[kk * NUM_HEADS + h], acc);
        }
        pos[t] = acc;
    }
    __syncthreads();
    for (int idx = t; idx < NTOK * BJP; idx += blockDim.x) {
        int i = idx / BJP;
        int j = idx % BJP;
        float val = 0.0f;
        if (j < NTOK) {
            int rel = (i / GS - j / GS + (GS - 1)) * (2 * GS - 1) + (i % GS - j % GS + (GS - 1));
            val = pos[rel];
        }
        g_biasH[(h * NTOK + i) * BJP + j] = __float2half(val);
    }
}

// ---------------- mma attention: CTA = 1 window, 4 warps x 16 rows ----------------
__global__ __launch_bounds__(128, 8)
void attn_mma(const float* __restrict__ q, const float* __restrict__ k,
              const float* __restrict__ v, float* __restrict__ out) {
    // smem: Khi | Klo | Vf16 (15360) + fp16 bias block (5488)
    __shared__ unsigned char sm[3 * MATB + BIASB];
    const int tid = threadIdx.x;
    const int lane = tid & 31;
    const int wid = tid >> 5;

    const int gwid = blockIdx.x;                 // window id = (b,h)
    const int h = gwid & 7;
    const long long base = (long long)(gwid >> 3) * (NTOK * CCH) + h * HDIM;

    __half* sB = (__half*)(sm + 3 * MATB);

    // ---- stage fp16 bias block for this head into smem (uint4, unrolled) ----
    {
        const uint4* gb = (const uint4*)(g_biasH + h * (NTOK * BJP));
        uint4* db = (uint4*)sB;
#pragma unroll
        for (int it = 0; it < 3; ++it) {
            int idx = tid + it * 128;            // 0..342
            if (idx < BIASB / 16) db[idx] = gb[idx];
        }
    }

    // ---- zero pad rows 49..63 of the V plane only (K pad is predicate-masked later) ----
    {
        const float4 z4 = make_float4(0.f, 0.f, 0.f, 0.f);
        if (tid < 75) {
            int row = 49 + tid / 5, c = tid % 5;
            *(float4*)(sm + 2 * MATB + row * STRB + c * 16) = z4;
        }
    }

    // ---- stage K (bf16 hi/lo), V (fp16) rows 0..48 — fully unrolled, LDGs batched ----
    {
        const int c = tid & 7;
        const int r0w = tid >> 3;                // 0..15
#pragma unroll
        for (int it = 0; it < 7; ++it) {
            int row = r0w + it * 16;             // 0..111
            if (row < 98) {
                int mat = (row >= 49) ? 1 : 0;   // 0 = K, 1 = V
                int r = row - 49 * mat;
                const float* src = mat ? v : k;
                float4 x = ((const float4*)(src + base + (long long)r * CCH))[c];
                if (mat == 0) {
                    uint32_t h0, l0, h1, l1;
                    split2(x.x, x.y, h0, l0);
                    split2(x.z, x.w, h1, l1);
                    unsigned char* dst = sm + r * STRB + c * 8;
                    *(uint2*)dst = make_uint2(h0, h1);
                    *(uint2*)(dst + MATB) = make_uint2(l0, l1);
                } else {
                    uint32_t a = packh2(x.x, x.y);
                    uint32_t b = packh2(x.z, x.w);
                    *(uint2*)(sm + 2 * MATB + r * STRB + c * 8) = make_uint2(a, b);
                }
            }
        }
    }
    __syncthreads();

    const uint32_t wsb = smem_u32(sm);
    const int r0 = wid * 16 + (lane >> 2);
    const int r1 = r0 + 8;
    const bool p0 = (r0 < NTOK), p1 = (r1 < NTOK);
    const float* q0 = q + base + (long long)r0 * CCH;
    const float* q1 = q + base + (long long)r1 * CCH;
    const int cb = 2 * (lane & 3);

    // ---- S = Qs.K^T : sacc[ntile(7)][4]; kk outer to keep only 8 Q-frag regs live ----
    float sacc[7][4];
#pragma unroll
    for (int nt = 0; nt < 7; ++nt)
#pragma unroll
        for (int e = 0; e < 4; ++e) sacc[nt][e] = 0.f;

    const uint32_t kAddrBase = wsb + ((lane & 7) + ((lane & 16) ? 8 : 0)) * STRB + ((lane & 8) ? 16 : 0);

#pragma unroll
    for (int kk = 0; kk < 2; ++kk) {
        // Q fragments for this 16-wide k-slice, straight from gmem (predicated)
        uint32_t qh[4], ql[4];
        {
            const float2 z2 = make_float2(0.f, 0.f);
            int c = cb + 16 * kk;
            float2 x0 = p0 ? *(const float2*)(q0 + c)     : z2;
            float2 x1 = p1 ? *(const float2*)(q1 + c)     : z2;
            float2 x2 = p0 ? *(const float2*)(q0 + c + 8) : z2;
            float2 x3 = p1 ? *(const float2*)(q1 + c + 8) : z2;
            split2(x0.x * SCALE, x0.y * SCALE, qh[0], ql[0]);
            split2(x1.x * SCALE, x1.y * SCALE, qh[1], ql[1]);
            split2(x2.x * SCALE, x2.y * SCALE, qh[2], ql[2]);
            split2(x3.x * SCALE, x3.y * SCALE, qh[3], ql[3]);
        }
#pragma unroll
        for (int p = 0; p < 4; ++p) {
            uint32_t kh[4], kl[4];
            uint32_t a = kAddrBase + p * (16 * STRB) + kk * 32;
            ldsm4(kh, a);
            ldsm4(kl, a + MATB);
#pragma unroll
            for (int nl = 0; nl < 2; ++nl) {
                int nt = 2 * p + nl;
                if (nt < 7) {
                    mma16816(sacc[nt], qh, &kh[2 * nl]);
                    mma16816(sacc[nt], qh, &kl[2 * nl]);
                    mma16816(sacc[nt], ql, &kh[2 * nl]);
                }
            }
        }
    }

    // ---- fp16 bias (from smem) + exp softmax (in fragments), deferred normalization ----
    float inv[2];
#pragma unroll
    for (int hh = 0; hh < 2; ++hh) {
        int i = wid * 16 + (lane >> 2) + hh * 8;
        bool vrow = (i < NTOK);
        const __half* bp = sB + (vrow ? i : 0) * BJP + cb;
        float rsum = 0.f;
#pragma unroll
        for (int nt = 0; nt < 7; ++nt) {
            float2 bb = __half22float2(*(const __half2*)(bp + 8 * nt));
            int j0 = 8 * nt + cb;
            float s0 = sacc[nt][2 * hh] + bb.x;
            float s1 = sacc[nt][2 * hh + 1] + bb.y;
            float e0 = (vrow && j0 < NTOK) ? __expf(s0) : 0.f;
            float e1 = (vrow && j0 + 1 < NTOK) ? __expf(s1) : 0.f;
            sacc[nt][2 * hh] = e0;
            sacc[nt][2 * hh + 1] = e1;
            rsum += e0 + e1;
        }
        rsum += __shfl_xor_sync(0xffffffffu, rsum, 1);
        rsum += __shfl_xor_sync(0xffffffffu, rsum, 2);
        inv[hh] = __fdividef(1.f, rsum);
    }

    // ---- O = P.V : fp16 x fp16, single-term ----
    float oacc[4][4];
#pragma unroll
    for (int n = 0; n < 4; ++n)
#pragma unroll
        for (int e = 0; e < 4; ++e) oacc[n][e] = 0.f;

    const uint32_t vAddrBase = wsb + 2 * MATB + (lane & 15) * STRB + (lane & 16);

#pragma unroll
    for (int kc = 0; kc < 4; ++kc) {
        uint32_t vh[2][4];
#pragma unroll
        for (int np = 0; np < 2; ++np)
            ldsm4t(vh[np], vAddrBase + kc * (16 * STRB) + np * 32);
        uint32_t ah[4];
        ah[0] = packh2(sacc[2 * kc][0], sacc[2 * kc][1]);
        ah[1] = packh2(sacc[2 * kc][2], sacc[2 * kc][3]);
        if (kc < 3) {
            ah[2] = packh2(sacc[2 * kc + 1][0], sacc[2 * kc + 1][1]);
            ah[3] = packh2(sacc[2 * kc + 1][2], sacc[2 * kc + 1][3]);
        } else {
            ah[2] = ah[3] = 0u;                  // keys 56-63 are pad
        }
#pragma unroll
        for (int n = 0; n < 4; ++n)
            mma16816h(oacc[n], ah, &vh[n >> 1][2 * (n & 1)]);
    }

    // ---- epilogue: normalize + store ----
#pragma unroll
    for (int hh = 0; hh < 2; ++hh) {
        int i = wid * 16 + (lane >> 2) + hh * 8;
        if (i < NTOK) {
            float* op = out + base + (long long)i * CCH + cb;
            float iv = inv[hh];
#pragma unroll
            for (int n = 0; n < 4; ++n) {
                float2 val = make_float2(oacc[n][2 * hh] * iv,
                                         oacc[n][2 * hh + 1] * iv);
                *(float2*)(op + 8 * n) = val;
            }
        }
    }
}

extern "C" void kernel_launch(void* const* d_in, const int* in_sizes, int n_in,
                              void* d_out, int out_size) {
    const float* q  = (const float*)d_in[0];
    const float* k  = (const float*)d_in[1];
    const float* v  = (const float*)d_in[2];
    const float* W1 = (const float*)d_in[3];
    const float* b1 = (const float*)d_in[4];
    const float* W2 = (const float*)d_in[5];
    const float* b2 = (const float*)d_in[6];
    float* out = (float*)d_out;

    const int B = in_sizes[0] / (NTOK * CCH);   // 2048
    const int nwin = B * NUM_HEADS;             // 16384

    bias_kernel<<<NUM_HEADS, 256>>>(W1, b1, W2, b2);
    attn_mma<<<nwin, 128>>>(q, k, v, out);
}

// round 13
// speedup vs baseline: 1.5765x; 1.0373x over previous
#include <cuda_runtime.h>
#include <cuda_fp16.h>
#include <cstdint>

#define NUM_HEADS 8
#define GS 7
#define NTOK 49
#define HDIM 32
#define CCH 256
#define NBIAS 169
#define HID 64
#define SCALE 0.17677669529663687f   // 32^-0.5
#define BJP 56                        // padded bias row length (halfs)
#define STRB 80                       // smem row stride (bytes), conflict-free for ldmatrix
#define MATB (64 * STRB)              // bytes per 64-row 16-bit matrix (5120)
#define BIASB (NTOK * BJP * 2)        // bias block bytes, fp16 (5488)

__device__ __half g_biasH[NUM_HEADS * NTOK * BJP];

// ---------------- helpers ----------------
__device__ __forceinline__ uint32_t smem_u32(const void* p) {
    uint32_t a;
    asm("{ .reg .u64 t; cvta.to.shared.u64 t, %1; cvt.u32.u64 %0, t; }" : "=r"(a) : "l"(p));
    return a;
}
__device__ __forceinline__ void ldsm4(uint32_t* r, uint32_t a) {
    asm volatile("ldmatrix.sync.aligned.m8n8.x4.shared.b16 {%0,%1,%2,%3}, [%4];"
                 : "=r"(r[0]), "=r"(r[1]), "=r"(r[2]), "=r"(r[3]) : "r"(a));
}
__device__ __forceinline__ void ldsm4t(uint32_t* r, uint32_t a) {
    asm volatile("ldmatrix.sync.aligned.m8n8.x4.trans.shared.b16 {%0,%1,%2,%3}, [%4];"
                 : "=r"(r[0]), "=r"(r[1]), "=r"(r[2]), "=r"(r[3]) : "r"(a));
}
__device__ __forceinline__ void mma16816(float* c, const uint32_t* a, const uint32_t* b) {
    asm volatile("mma.sync.aligned.m16n8k16.row.col.f32.bf16.bf16.f32 "
                 "{%0,%1,%2,%3}, {%4,%5,%6,%7}, {%8,%9}, {%0,%1,%2,%3};"
                 : "+f"(c[0]), "+f"(c[1]), "+f"(c[2]), "+f"(c[3])
                 : "r"(a[0]), "r"(a[1]), "r"(a[2]), "r"(a[3]), "r"(b[0]), "r"(b[1]));
}
__device__ __forceinline__ void mma16816h(float* c, const uint32_t* a, const uint32_t* b) {
    asm volatile("mma.sync.aligned.m16n8k16.row.col.f32.f16.f16.f32 "
                 "{%0,%1,%2,%3}, {%4,%5,%6,%7}, {%8,%9}, {%0,%1,%2,%3};"
                 : "+f"(c[0]), "+f"(c[1]), "+f"(c[2]), "+f"(c[3])
                 : "r"(a[0]), "r"(a[1]), "r"(a[2]), "r"(a[3]), "r"(b[0]), "r"(b[1]));
}
// pack (lo,hi) floats -> bf16x2 (lo in low half)
__device__ __forceinline__ uint32_t packbf(float lo, float hi) {
    uint32_t d;
    asm("cvt.rn.bf16x2.f32 %0, %1, %2;" : "=r"(d) : "f"(hi), "f"(lo));
    return d;
}
// pack (lo,hi) floats -> f16x2 (lo in low half)
__device__ __forceinline__ uint32_t packh2(float lo, float hi) {
    uint32_t d;
    asm("cvt.rn.f16x2.f32 %0, %1, %2;" : "=r"(d) : "f"(hi), "f"(lo));
    return d;
}
// split pair into bf16 hi part + bf16 residual part
__device__ __forceinline__ void split2(float e0, float e1, uint32_t& hi, uint32_t& lo) {
    hi = packbf(e0, e1);
    float h0 = __uint_as_float(hi << 16);
    float h1 = __uint_as_float(hi & 0xFFFF0000u);
    lo = packbf(e0 - h0, e1 - h1);
}

// ---------------- bias precompute: [h][i][j] fp16, padded to 56 cols ----------------
__global__ void bias_kernel(const float* __restrict__ W1, const float* __restrict__ b1,
                            const float* __restrict__ W2, const float* __restrict__ b2) {
    __shared__ float pos[NBIAS];
    const int h = blockIdx.x;
    const int t = threadIdx.x;
    if (t < NBIAS) {
        float bh = (float)(t / (2 * GS - 1)) - (float)(GS - 1);
        float bw = (float)(t % (2 * GS - 1)) - (float)(GS - 1);
        float acc = b2[h];
        for (int kk = 0; kk < HID; ++kk) {
            float hv = fmaxf(fmaf(bh, W1[kk], fmaf(bw, W1[HID + kk], b1[kk])), 0.0f);
            acc = fmaf(hv, W2[kk * NUM_HEADS + h], acc);
        }
        pos[t] = acc;
    }
    __syncthreads();
    for (int idx = t; idx < NTOK * BJP; idx += blockDim.x) {
        int i = idx / BJP;
        int j = idx % BJP;
        float val = 0.0f;
        if (j < NTOK) {
            int rel = (i / GS - j / GS + (GS - 1)) * (2 * GS - 1) + (i % GS - j % GS + (GS - 1));
            val = pos[rel];
        }
        g_biasH[(h * NTOK + i) * BJP + j] = __float2half(val);
    }
}

// ---------------- mma attention: CTA = 1 window, 4 warps x 16 rows ----------------
// k-dim permutation: mma col (16kk + 2t + d + 8e) holds gmem col (16kk + 4t + 2e + d)
// d-dim permutation: V smem pos (2t + 8n + d) holds gmem col (8t + 2n + d)
__global__ __launch_bounds__(128, 8)
void attn_mma(const float* __restrict__ q, const float* __restrict__ k,
              const float* __restrict__ v, float* __restrict__ out) {
    // smem: Khi | Klo | Vf16 (15360) + fp16 bias block (5488)
    __shared__ unsigned char sm[3 * MATB + BIASB];
    const int tid = threadIdx.x;
    const int lane = tid & 31;
    const int wid = tid >> 5;

    const int gwid = blockIdx.x;                 // window id = (b,h)
    const int h = gwid & 7;
    const long long base = (long long)(gwid >> 3) * (NTOK * CCH) + h * HDIM;

    __half* sB = (__half*)(sm + 3 * MATB);

    // ---- stage fp16 bias block for this head into smem (uint4, unrolled) ----
    {
        const uint4* gb = (const uint4*)(g_biasH + h * (NTOK * BJP));
        uint4* db = (uint4*)sB;
#pragma unroll
        for (int it = 0; it < 3; ++it) {
            int idx = tid + it * 128;            // 0..342
            if (idx < BIASB / 16) db[idx] = gb[idx];
        }
    }

    // ---- zero pad rows 49..63 of the V plane only (K pad is predicate-masked later) ----
    {
        const float4 z4 = make_float4(0.f, 0.f, 0.f, 0.f);
        if (tid < 75) {
            int row = 49 + tid / 5, c = tid % 5;
            *(float4*)(sm + 2 * MATB + row * STRB + c * 16) = z4;
        }
    }

    // ---- stage K (bf16 hi/lo, k-permuted), V (fp16, d-permuted) rows 0..48 ----
    {
        const int c = tid & 7;
        const int r0w = tid >> 3;                // 0..15
        // K scatter offsets: kk = c>>2, t = c&3 -> byte 32*kk + 4*t, pair2 at +16
        const int koff = 32 * (c >> 2) + 4 * (c & 3);
        // V scatter offsets: t = c>>1, g = c&1 -> byte 4*t + 32*g, pair2 at +16
        const int voff = 4 * (c >> 1) + 32 * (c & 1);
#pragma unroll
        for (int it = 0; it < 7; ++it) {
            int row = r0w + it * 16;             // 0..111
            if (row < 98) {
                int mat = (row >= 49) ? 1 : 0;   // 0 = K, 1 = V
                int r = row - 49 * mat;
                const float* src = mat ? v : k;
                float4 x = ((const float4*)(src + base + (long long)r * CCH))[c];
                if (mat == 0) {
                    uint32_t h01, l01, h23, l23;
                    split2(x.x, x.y, h01, l01);
                    split2(x.z, x.w, h23, l23);
                    unsigned char* dst = sm + r * STRB + koff;
                    *(uint32_t*)dst = h01;
                    *(uint32_t*)(dst + 16) = h23;
                    *(uint32_t*)(dst + MATB) = l01;
                    *(uint32_t*)(dst + MATB + 16) = l23;
                } else {
                    unsigned char* dst = sm + 2 * MATB + r * STRB + voff;
                    *(uint32_t*)dst = packh2(x.x, x.y);
                    *(uint32_t*)(dst + 16) = packh2(x.z, x.w);
                }
            }
        }
    }
    __syncthreads();

    const uint32_t wsb = smem_u32(sm);
    const int r0 = wid * 16 + (lane >> 2);
    const int r1 = r0 + 8;
    const bool p0 = (r0 < NTOK), p1 = (r1 < NTOK);
    const float* q0 = q + base + (long long)r0 * CCH;
    const float* q1 = q + base + (long long)r1 * CCH;
    const int tq = lane & 3;
    const int cb = 2 * tq;

    // ---- S = Qs.K^T : sacc[ntile(7)][4]; kk outer to keep only 8 Q-frag regs live ----
    float sacc[7][4];
#pragma unroll
    for (int nt = 0; nt < 7; ++nt)
#pragma unroll
        for (int e = 0; e < 4; ++e) sacc[nt][e] = 0.f;

    const uint32_t kAddrBase = wsb + ((lane & 7) + ((lane & 16) ? 8 : 0)) * STRB + ((lane & 8) ? 16 : 0);

#pragma unroll
    for (int kk = 0; kk < 2; ++kk) {
        // Q fragments: one float4 per row covers the thread's 4 fragment elements (k-permuted)
        uint32_t qh[4], ql[4];
        {
            const float4 z4 = make_float4(0.f, 0.f, 0.f, 0.f);
            int c = 16 * kk + 4 * tq;
            float4 x0 = p0 ? *(const float4*)(q0 + c) : z4;
            float4 x1 = p1 ? *(const float4*)(q1 + c) : z4;
            split2(x0.x * SCALE, x0.y * SCALE, qh[0], ql[0]);
            split2(x1.x * SCALE, x1.y * SCALE, qh[1], ql[1]);
            split2(x0.z * SCALE, x0.w * SCALE, qh[2], ql[2]);
            split2(x1.z * SCALE, x1.w * SCALE, qh[3], ql[3]);
        }
#pragma unroll
        for (int p = 0; p < 4; ++p) {
            uint32_t kh[4], kl[4];
            uint32_t a = kAddrBase + p * (16 * STRB) + kk * 32;
            ldsm4(kh, a);
            ldsm4(kl, a + MATB);
#pragma unroll
            for (int nl = 0; nl < 2; ++nl) {
                int nt = 2 * p + nl;
                if (nt < 7) {
                    mma16816(sacc[nt], qh, &kh[2 * nl]);
                    mma16816(sacc[nt], qh, &kl[2 * nl]);
                    mma16816(sacc[nt], ql, &kh[2 * nl]);
                }
            }
        }
    }

    // ---- fp16 bias (from smem) + exp softmax (in fragments), deferred normalization ----
    float inv[2];
#pragma unroll
    for (int hh = 0; hh < 2; ++hh) {
        int i = wid * 16 + (lane >> 2) + hh * 8;
        bool vrow = (i < NTOK);
        const __half* bp = sB + (vrow ? i : 0) * BJP + cb;
        float rsum = 0.f;
#pragma unroll
        for (int nt = 0; nt < 7; ++nt) {
            float2 bb = __half22float2(*(const __half2*)(bp + 8 * nt));
            int j0 = 8 * nt + cb;
            float s0 = sacc[nt][2 * hh] + bb.x;
            float s1 = sacc[nt][2 * hh + 1] + bb.y;
            float e0 = (vrow && j0 < NTOK) ? __expf(s0) : 0.f;
            float e1 = (vrow && j0 + 1 < NTOK) ? __expf(s1) : 0.f;
            sacc[nt][2 * hh] = e0;
            sacc[nt][2 * hh + 1] = e1;
            rsum += e0 + e1;
        }
        rsum += __shfl_xor_sync(0xffffffffu, rsum, 1);
        rsum += __shfl_xor_sync(0xffffffffu, rsum, 2);
        inv[hh] = __fdividef(1.f, rsum);
    }

    // ---- O = P.V : fp16 x fp16, single-term ----
    float oacc[4][4];
#pragma unroll
    for (int n = 0; n < 4; ++n)
#pragma unroll
        for (int e = 0; e < 4; ++e) oacc[n][e] = 0.f;

    const uint32_t vAddrBase = wsb + 2 * MATB + (lane & 15) * STRB + (lane & 16);

#pragma unroll
    for (int kc = 0; kc < 4; ++kc) {
        uint32_t vh[2][4];
#pragma unroll
        for (int np = 0; np < 2; ++np)
            ldsm4t(vh[np], vAddrBase + kc * (16 * STRB) + np * 32);
        uint32_t ah[4];
        ah[0] = packh2(sacc[2 * kc][0], sacc[2 * kc][1]);
        ah[1] = packh2(sacc[2 * kc][2], sacc[2 * kc][3]);
        if (kc < 3) {
            ah[2] = packh2(sacc[2 * kc + 1][0], sacc[2 * kc + 1][1]);
            ah[3] = packh2(sacc[2 * kc + 1][2], sacc[2 * kc + 1][3]);
        } else {
            ah[2] = ah[3] = 0u;                  // keys 56-63 are pad
        }
#pragma unroll
        for (int n = 0; n < 4; ++n)
            mma16816h(oacc[n], ah, &vh[n >> 1][2 * (n & 1)]);
    }

    // ---- epilogue: normalize + store (d-permutation -> 2 contiguous float4 per row) ----
#pragma unroll
    for (int hh = 0; hh < 2; ++hh) {
        int i = wid * 16 + (lane >> 2) + hh * 8;
        if (i < NTOK) {
            float* op = out + base + (long long)i * CCH + 8 * tq;
            float iv = inv[hh];
            float4 o1, o2;
            o1.x = oacc[0][2 * hh]     * iv;
            o1.y = oacc[0][2 * hh + 1] * iv;
            o1.z = oacc[1][2 * hh]     * iv;
            o1.w = oacc[1][2 * hh + 1] * iv;
            o2.x = oacc[2][2 * hh]     * iv;
            o2.y = oacc[2][2 * hh + 1] * iv;
            o2.z = oacc[3][2 * hh]     * iv;
            o2.w = oacc[3][2 * hh + 1] * iv;
            *(float4*)op = o1;
            *(float4*)(op + 4) = o2;
        }
    }
}

extern "C" void kernel_launch(void* const* d_in, const int* in_sizes, int n_in,
                              void* d_out, int out_size) {
    const float* q  = (const float*)d_in[0];
    const float* k  = (const float*)d_in[1];
    const float* v  = (const float*)d_in[2];
    const float* W1 = (const float*)d_in[3];
    const float* b1 = (const float*)d_in[4];
    const float* W2 = (const float*)d_in[5];
    const float* b2 = (const float*)d_in[6];
    float* out = (float*)d_out;

    const int B = in_sizes[0] / (NTOK * CCH);   // 2048
    const int nwin = B * NUM_HEADS;             // 16384

    bias_kernel<<<NUM_HEADS, 256>>>(W1, b1, W2, b2);
    attn_mma<<<nwin, 128>>>(q, k, v, out);
}

// round 14
// speedup vs baseline: 1.6428x; 1.0421x over previous
#include <cuda_runtime.h>
#include <cuda_fp16.h>
#include <cstdint>

#define NUM_HEADS 8
#define GS 7
#define NTOK 49
#define HDIM 32
#define CCH 256
#define NBIAS 169
#define HID 64
#define SCALE 0.17677669529663687f   // 32^-0.5
#define LOG2E 1.4426950408889634f
#define QSC (SCALE * LOG2E)           // fold softmax exp base conversion into Q
#define BJP 56                        // padded bias row length (halfs)
#define STRB 80                       // smem row stride (bytes), conflict-free for ldmatrix
#define MATB (64 * STRB)              // bytes per 64-row 16-bit matrix (5120)
#define BIASB (NTOK * BJP * 2)        // bias block bytes, fp16 (5488)

__device__ __half g_biasH[NUM_HEADS * NTOK * BJP];

// ---------------- helpers ----------------
__device__ __forceinline__ uint32_t smem_u32(const void* p) {
    uint32_t a;
    asm("{ .reg .u64 t; cvta.to.shared.u64 t, %1; cvt.u32.u64 %0, t; }" : "=r"(a) : "l"(p));
    return a;
}
__device__ __forceinline__ void ldsm4(uint32_t* r, uint32_t a) {
    asm volatile("ldmatrix.sync.aligned.m8n8.x4.shared.b16 {%0,%1,%2,%3}, [%4];"
                 : "=r"(r[0]), "=r"(r[1]), "=r"(r[2]), "=r"(r[3]) : "r"(a));
}
__device__ __forceinline__ void ldsm4t(uint32_t* r, uint32_t a) {
    asm volatile("ldmatrix.sync.aligned.m8n8.x4.trans.shared.b16 {%0,%1,%2,%3}, [%4];"
                 : "=r"(r[0]), "=r"(r[1]), "=r"(r[2]), "=r"(r[3]) : "r"(a));
}
__device__ __forceinline__ void mma16816(float* c, const uint32_t* a, const uint32_t* b) {
    asm volatile("mma.sync.aligned.m16n8k16.row.col.f32.bf16.bf16.f32 "
                 "{%0,%1,%2,%3}, {%4,%5,%6,%7}, {%8,%9}, {%0,%1,%2,%3};"
                 : "+f"(c[0]), "+f"(c[1]), "+f"(c[2]), "+f"(c[3])
                 : "r"(a[0]), "r"(a[1]), "r"(a[2]), "r"(a[3]), "r"(b[0]), "r"(b[1]));
}
__device__ __forceinline__ void mma16816h(float* c, const uint32_t* a, const uint32_t* b) {
    asm volatile("mma.sync.aligned.m16n8k16.row.col.f32.f16.f16.f32 "
                 "{%0,%1,%2,%3}, {%4,%5,%6,%7}, {%8,%9}, {%0,%1,%2,%3};"
                 : "+f"(c[0]), "+f"(c[1]), "+f"(c[2]), "+f"(c[3])
                 : "r"(a[0]), "r"(a[1]), "r"(a[2]), "r"(a[3]), "r"(b[0]), "r"(b[1]));
}
// pack (lo,hi) floats -> bf16x2 (lo in low half)
__device__ __forceinline__ uint32_t packbf(float lo, float hi) {
    uint32_t d;
    asm("cvt.rn.bf16x2.f32 %0, %1, %2;" : "=r"(d) : "f"(hi), "f"(lo));
    return d;
}
// pack (lo,hi) floats -> f16x2 (lo in low half)
__device__ __forceinline__ uint32_t packh2(float lo, float hi) {
    uint32_t d;
    asm("cvt.rn.f16x2.f32 %0, %1, %2;" : "=r"(d) : "f"(hi), "f"(lo));
    return d;
}
// split pair into bf16 hi part + bf16 residual part
__device__ __forceinline__ void split2(float e0, float e1, uint32_t& hi, uint32_t& lo) {
    hi = packbf(e0, e1);
    float h0 = __uint_as_float(hi << 16);
    float h1 = __uint_as_float(hi & 0xFFFF0000u);
    lo = packbf(e0 - h0, e1 - h1);
}

// ------- bias precompute: [h][i][j] fp16, x log2e, pad cols = -30000 (mask) -------
__global__ void bias_kernel(const float* __restrict__ W1, const float* __restrict__ b1,
                            const float* __restrict__ W2, const float* __restrict__ b2) {
    __shared__ float pos[NBIAS];
    const int h = blockIdx.x;
    const int t = threadIdx.x;
    if (t < NBIAS) {
        float bh = (float)(t / (2 * GS - 1)) - (float)(GS - 1);
        float bw = (float)(t % (2 * GS - 1)) - (float)(GS - 1);
        float acc = b2[h];
        for (int kk = 0; kk < HID; ++kk) {
            float hv = fmaxf(fmaf(bh, W1[kk], fmaf(bw, W1[HID + kk], b1[kk])), 0.0f);
            acc = fmaf(hv, W2[kk * NUM_HEADS + h], acc);
        }
        pos[t] = acc;
    }
    __syncthreads();
    for (int idx = t; idx < NTOK * BJP; idx += blockDim.x) {
        int i = idx / BJP;
        int j = idx % BJP;
        float val = -30000.0f;                   // pad columns: exp2 -> 0
        if (j < NTOK) {
            int rel = (i / GS - j / GS + (GS - 1)) * (2 * GS - 1) + (i % GS - j % GS + (GS - 1));
            val = pos[rel] * LOG2E;
        }
        g_biasH[(h * NTOK + i) * BJP + j] = __float2half(val);
    }
}

// ---------------- mma attention: CTA = 1 window, 4 warps x 16 rows ----------------
// k-dim permutation: mma col (16kk + 2t + d + 8e) holds gmem col (16kk + 4t + 2e + d)
// d-dim permutation: V smem pos (2t + 8n + d) holds gmem col (8t + 2n + d)
__global__ __launch_bounds__(128, 8)
void attn_mma(const float* __restrict__ q, const float* __restrict__ k,
              const float* __restrict__ v, float* __restrict__ out) {
    // smem: Khi | Klo | Vf16 (15360) + fp16 bias block (5488)
    __shared__ unsigned char sm[3 * MATB + BIASB];
    const int tid = threadIdx.x;
    const int lane = tid & 31;
    const int wid = tid >> 5;

    const int gwid = blockIdx.x;                 // window id = (b,h)
    const int h = gwid & 7;
    const long long base = (long long)(gwid >> 3) * (NTOK * CCH) + h * HDIM;

    __half* sB = (__half*)(sm + 3 * MATB);

    // ---- stage fp16 bias block for this head into smem (uint4, unrolled) ----
    {
        const uint4* gb = (const uint4*)(g_biasH + h * (NTOK * BJP));
        uint4* db = (uint4*)sB;
#pragma unroll
        for (int it = 0; it < 3; ++it) {
            int idx = tid + it * 128;            // 0..342
            if (idx < BIASB / 16) db[idx] = gb[idx];
        }
    }

    // ---- zero pad rows 49..63 of Khi, Klo, V (bias mask requires clean K pad) ----
    {
        const float4 z4 = make_float4(0.f, 0.f, 0.f, 0.f);
#pragma unroll
        for (int it = 0; it < 2; ++it) {
            int idx = tid + it * 128;            // need 225
            if (idx < 225) {
                int m = idx / 75, rem = idx % 75;
                int row = 49 + rem / 5, c = rem % 5;
                *(float4*)(sm + m * MATB + row * STRB + c * 16) = z4;
            }
        }
    }

    // ---- stage K (bf16 hi/lo, k-permuted), V (fp16, d-permuted) rows 0..48 ----
    {
        const int c = tid & 7;
        const int r0w = tid >> 3;                // 0..15
        // K scatter offsets: kk = c>>2, t = c&3 -> byte 32*kk + 4*t, pair2 at +16
        const int koff = 32 * (c >> 2) + 4 * (c & 3);
        // V scatter offsets: t = c>>1, g = c&1 -> byte 4*t + 32*g, pair2 at +16
        const int voff = 4 * (c >> 1) + 32 * (c & 1);
#pragma unroll
        for (int it = 0; it < 7; ++it) {
            int row = r0w + it * 16;             // 0..111
            if (row < 98) {
                int mat = (row >= 49) ? 1 : 0;   // 0 = K, 1 = V
                int r = row - 49 * mat;
                const float* src = mat ? v : k;
                float4 x = ((const float4*)(src + base + (long long)r * CCH))[c];
                if (mat == 0) {
                    uint32_t h01, l01, h23, l23;
                    split2(x.x, x.y, h01, l01);
                    split2(x.z, x.w, h23, l23);
                    unsigned char* dst = sm + r * STRB + koff;
                    *(uint32_t*)dst = h01;
                    *(uint32_t*)(dst + 16) = h23;
                    *(uint32_t*)(dst + MATB) = l01;
                    *(uint32_t*)(dst + MATB + 16) = l23;
                } else {
                    unsigned char* dst = sm + 2 * MATB + r * STRB + voff;
                    *(uint32_t*)dst = packh2(x.x, x.y);
                    *(uint32_t*)(dst + 16) = packh2(x.z, x.w);
                }
            }
        }
    }
    __syncthreads();

    const uint32_t wsb = smem_u32(sm);
    const int r0 = wid * 16 + (lane >> 2);
    const int r1 = r0 + 8;
    const bool p0 = (r0 < NTOK), p1 = (r1 < NTOK);
    const float* q0 = q + base + (long long)r0 * CCH;
    const float* q1 = q + base + (long long)r1 * CCH;
    const int tq = lane & 3;
    const int cb = 2 * tq;

    // ---- S = (Qs*log2e).K^T : sacc[ntile(7)][4] ----
    float sacc[7][4];
#pragma unroll
    for (int nt = 0; nt < 7; ++nt)
#pragma unroll
        for (int e = 0; e < 4; ++e) sacc[nt][e] = 0.f;

    const uint32_t kAddrBase = wsb + ((lane & 7) + ((lane & 16) ? 8 : 0)) * STRB + ((lane & 8) ? 16 : 0);

#pragma unroll
    for (int kk = 0; kk < 2; ++kk) {
        // Q fragments: one float4 per row covers the thread's 4 fragment elements (k-permuted)
        uint32_t qh[4], ql[4];
        {
            const float4 z4 = make_float4(0.f, 0.f, 0.f, 0.f);
            int c = 16 * kk + 4 * tq;
            float4 x0 = p0 ? *(const float4*)(q0 + c) : z4;
            float4 x1 = p1 ? *(const float4*)(q1 + c) : z4;
            split2(x0.x * QSC, x0.y * QSC, qh[0], ql[0]);
            split2(x1.x * QSC, x1.y * QSC, qh[1], ql[1]);
            split2(x0.z * QSC, x0.w * QSC, qh[2], ql[2]);
            split2(x1.z * QSC, x1.w * QSC, qh[3], ql[3]);
        }
#pragma unroll
        for (int p = 0; p < 4; ++p) {
            uint32_t kh[4], kl[4];
            uint32_t a = kAddrBase + p * (16 * STRB) + kk * 32;
            ldsm4(kh, a);
            ldsm4(kl, a + MATB);
#pragma unroll
            for (int nl = 0; nl < 2; ++nl) {
                int nt = 2 * p + nl;
                if (nt < 7) {
                    mma16816(sacc[nt], qh, &kh[2 * nl]);
                    mma16816(sacc[nt], qh, &kl[2 * nl]);
                    mma16816(sacc[nt], ql, &kh[2 * nl]);
                }
            }
        }
    }

    // ---- softmax: exp2(s + bias), pad columns auto-masked by bias = -30000 ----
    float inv[2];
#pragma unroll
    for (int hh = 0; hh < 2; ++hh) {
        int i = wid * 16 + (lane >> 2) + hh * 8;
        bool vrow = (i < NTOK);
        const __half* bp = sB + (vrow ? i : 0) * BJP + cb;
        float rsum = 0.f;
#pragma unroll
        for (int nt = 0; nt < 7; ++nt) {
            float2 bb = __half22float2(*(const __half2*)(bp + 8 * nt));
            float e0 = exp2f(sacc[nt][2 * hh] + bb.x);
            float e1 = exp2f(sacc[nt][2 * hh + 1] + bb.y);
            sacc[nt][2 * hh] = e0;
            sacc[nt][2 * hh + 1] = e1;
            rsum += e0 + e1;
        }
        rsum += __shfl_xor_sync(0xffffffffu, rsum, 1);
        rsum += __shfl_xor_sync(0xffffffffu, rsum, 2);
        inv[hh] = __fdividef(1.f, rsum);
    }

    // ---- O = P.V : fp16 x fp16, single-term ----
    float oacc[4][4];
#pragma unroll
    for (int n = 0; n < 4; ++n)
#pragma unroll
        for (int e = 0; e < 4; ++e) oacc[n][e] = 0.f;

    const uint32_t vAddrBase = wsb + 2 * MATB + (lane & 15) * STRB + (lane & 16);

#pragma unroll
    for (int kc = 0; kc < 4; ++kc) {
        uint32_t vh[2][4];
#pragma unroll
        for (int np = 0; np < 2; ++np)
            ldsm4t(vh[np], vAddrBase + kc * (16 * STRB) + np * 32);
        uint32_t ah[4];
        ah[0] = packh2(sacc[2 * kc][0], sacc[2 * kc][1]);
        ah[1] = packh2(sacc[2 * kc][2], sacc[2 * kc][3]);
        if (kc < 3) {
            ah[2] = packh2(sacc[2 * kc + 1][0], sacc[2 * kc + 1][1]);
            ah[3] = packh2(sacc[2 * kc + 1][2], sacc[2 * kc + 1][3]);
        } else {
            ah[2] = ah[3] = 0u;                  // keys 56-63 are pad
        }
#pragma unroll
        for (int n = 0; n < 4; ++n)
            mma16816h(oacc[n], ah, &vh[n >> 1][2 * (n & 1)]);
    }

    // ---- epilogue: normalize + store (d-permutation -> 2 contiguous float4 per row) ----
#pragma unroll
    for (int hh = 0; hh < 2; ++hh) {
        int i = wid * 16 + (lane >> 2) + hh * 8;
        if (i < NTOK) {
            float* op = out + base + (long long)i * CCH + 8 * tq;
            float iv = inv[hh];
            float4 o1, o2;
            o1.x = oacc[0][2 * hh]     * iv;
            o1.y = oacc[0][2 * hh + 1] * iv;
            o1.z = oacc[1][2 * hh]     * iv;
            o1.w = oacc[1][2 * hh + 1] * iv;
            o2.x = oacc[2][2 * hh]     * iv;
            o2.y = oacc[2][2 * hh + 1] * iv;
            o2.z = oacc[3][2 * hh]     * iv;
            o2.w = oacc[3][2 * hh + 1] * iv;
            *(float4*)op = o1;
            *(float4*)(op + 4) = o2;
        }
    }
}

extern "C" void kernel_launch(void* const* d_in, const int* in_sizes, int n_in,
                              void* d_out, int out_size) {
    const float* q  = (const float*)d_in[0];
    const float* k  = (const float*)d_in[1];
    const float* v  = (const float*)d_in[2];
    const float* W1 = (const float*)d_in[3];
    const float* b1 = (const float*)d_in[4];
    const float* W2 = (const float*)d_in[5];
    const float* b2 = (const float*)d_in[6];
    float* out = (float*)d_out;

    const int B = in_sizes[0] / (NTOK * CCH);   // 2048
    const int nwin = B * NUM_HEADS;             // 16384

    bias_kernel<<<NUM_HEADS, 256>>>(W1, b1, W2, b2);
    attn_mma<<<nwin, 128>>>(q, k, v, out);
}

// round 15
// speedup vs baseline: 1.7893x; 1.0892x over previous
#include <cuda_runtime.h>
#include <cuda_fp16.h>
#include <cstdint>

#define NUM_HEADS 8
#define GS 7
#define NTOK 49
#define HDIM 32
#define CCH 256
#define NBIAS 169
#define HID 64
#define SCALE 0.17677669529663687f   // 32^-0.5
#define LOG2E 1.4426950408889634f
#define QSC (SCALE * LOG2E)           // fold softmax exp base conversion into Q
#define BJP 56                        // padded bias row length (halfs)
#define STRB 80                       // smem row stride (bytes), conflict-free for ldmatrix
#define MATB (64 * STRB)              // bytes per 64-row 16-bit matrix (5120)
#define BIASB (NTOK * BJP * 2)        // bias block bytes, fp16 (5488)

__device__ __half g_biasH[NUM_HEADS * NTOK * BJP];

// ---------------- helpers ----------------
__device__ __forceinline__ uint32_t smem_u32(const void* p) {
    uint32_t a;
    asm("{ .reg .u64 t; cvta.to.shared.u64 t, %1; cvt.u32.u64 %0, t; }" : "=r"(a) : "l"(p));
    return a;
}
__device__ __forceinline__ void ldsm4(uint32_t* r, uint32_t a) {
    asm volatile("ldmatrix.sync.aligned.m8n8.x4.shared.b16 {%0,%1,%2,%3}, [%4];"
                 : "=r"(r[0]), "=r"(r[1]), "=r"(r[2]), "=r"(r[3]) : "r"(a));
}
__device__ __forceinline__ void ldsm4t(uint32_t* r, uint32_t a) {
    asm volatile("ldmatrix.sync.aligned.m8n8.x4.trans.shared.b16 {%0,%1,%2,%3}, [%4];"
                 : "=r"(r[0]), "=r"(r[1]), "=r"(r[2]), "=r"(r[3]) : "r"(a));
}
__device__ __forceinline__ void mma16816h(float* c, const uint32_t* a, const uint32_t* b) {
    asm volatile("mma.sync.aligned.m16n8k16.row.col.f32.f16.f16.f32 "
                 "{%0,%1,%2,%3}, {%4,%5,%6,%7}, {%8,%9}, {%0,%1,%2,%3};"
                 : "+f"(c[0]), "+f"(c[1]), "+f"(c[2]), "+f"(c[3])
                 : "r"(a[0]), "r"(a[1]), "r"(a[2]), "r"(a[3]), "r"(b[0]), "r"(b[1]));
}
// pack (lo,hi) floats -> f16x2 (lo in low half)
__device__ __forceinline__ uint32_t packh2(float lo, float hi) {
    uint32_t d;
    asm("cvt.rn.f16x2.f32 %0, %1, %2;" : "=r"(d) : "f"(hi), "f"(lo));
    return d;
}
// split pair into fp16 hi part + fp16 residual part
__device__ __forceinline__ void splith(float e0, float e1, uint32_t& hi, uint32_t& lo) {
    hi = packh2(e0, e1);
    float2 f = __half22float2(*(const __half2*)&hi);
    lo = packh2(e0 - f.x, e1 - f.y);
}

// ------- bias precompute: [h][i][j] fp16, x log2e, pad cols = -30000 (mask) -------
__global__ void bias_kernel(const float* __restrict__ W1, const float* __restrict__ b1,
                            const float* __restrict__ W2, const float* __restrict__ b2) {
    __shared__ float pos[NBIAS];
    const int h = blockIdx.x;
    const int t = threadIdx.x;
    if (t < NBIAS) {
        float bh = (float)(t / (2 * GS - 1)) - (float)(GS - 1);
        float bw = (float)(t % (2 * GS - 1)) - (float)(GS - 1);
        float acc = b2[h];
        for (int kk = 0; kk < HID; ++kk) {
            float hv = fmaxf(fmaf(bh, W1[kk], fmaf(bw, W1[HID + kk], b1[kk])), 0.0f);
            acc = fmaf(hv, W2[kk * NUM_HEADS + h], acc);
        }
        pos[t] = acc;
    }
    __syncthreads();
    for (int idx = t; idx < NTOK * BJP; idx += blockDim.x) {
        int i = idx / BJP;
        int j = idx % BJP;
        float val = -30000.0f;                   // pad columns: exp2 -> 0
        if (j < NTOK) {
            int rel = (i / GS - j / GS + (GS - 1)) * (2 * GS - 1) + (i % GS - j % GS + (GS - 1));
            val = pos[rel] * LOG2E;
        }
        g_biasH[(h * NTOK + i) * BJP + j] = __float2half(val);
    }
}

// ---------------- mma attention: CTA = 1 window, 4 warps x 16 rows ----------------
// k-dim permutation: mma col (16kk + 2t + d + 8e) holds gmem col (16kk + 4t + 2e + d)
// d-dim permutation: V smem pos (2t + 8n + d) holds gmem col (8t + 2n + d)
// K: single fp16 plane (score error ~1e-4, SCALE-damped); Q: fp16 hi+residual (exact)
__global__ __launch_bounds__(128, 8)
void attn_mma(const float* __restrict__ q, const float* __restrict__ k,
              const float* __restrict__ v, float* __restrict__ out) {
    // smem: Kf16 | Vf16 (10240) + fp16 bias block (5488)
    __shared__ unsigned char sm[2 * MATB + BIASB];
    const int tid = threadIdx.x;
    const int lane = tid & 31;
    const int wid = tid >> 5;

    const int gwid = blockIdx.x;                 // window id = (b,h)
    const int h = gwid & 7;
    const long long base = (long long)(gwid >> 3) * (NTOK * CCH) + h * HDIM;

    __half* sB = (__half*)(sm + 2 * MATB);

    // ---- stage fp16 bias block for this head into smem (uint4, unrolled) ----
    {
        const uint4* gb = (const uint4*)(g_biasH + h * (NTOK * BJP));
        uint4* db = (uint4*)sB;
#pragma unroll
        for (int it = 0; it < 3; ++it) {
            int idx = tid + it * 128;            // 0..342
            if (idx < BIASB / 16) db[idx] = gb[idx];
        }
    }

    // ---- zero pad rows 49..63 of K and V planes ----
    {
        const float4 z4 = make_float4(0.f, 0.f, 0.f, 0.f);
#pragma unroll
        for (int it = 0; it < 2; ++it) {
            int idx = tid + it * 128;            // need 150
            if (idx < 150) {
                int m = idx / 75, rem = idx % 75;
                int row = 49 + rem / 5, c = rem % 5;
                *(float4*)(sm + m * MATB + row * STRB + c * 16) = z4;
            }
        }
    }

    // ---- stage K (fp16, k-permuted), V (fp16, d-permuted) rows 0..48 ----
    {
        const int c = tid & 7;
        const int r0w = tid >> 3;                // 0..15
        // K scatter: kk = c>>2, t = c&3 -> byte 32*kk + 4*t, pair2 at +16
        const int koff = 32 * (c >> 2) + 4 * (c & 3);
        // V scatter: t = c>>1, g = c&1 -> byte 4*t + 32*g, pair2 at +16
        const int voff = 4 * (c >> 1) + 32 * (c & 1);
#pragma unroll
        for (int it = 0; it < 7; ++it) {
            int row = r0w + it * 16;             // 0..111
            if (row < 98) {
                int mat = (row >= 49) ? 1 : 0;   // 0 = K, 1 = V
                int r = row - 49 * mat;
                const float* src = mat ? v : k;
                float4 x = ((const float4*)(src + base + (long long)r * CCH))[c];
                unsigned char* dst = sm + mat * MATB + r * STRB + (mat ? voff : koff);
                *(uint32_t*)dst = packh2(x.x, x.y);
                *(uint32_t*)(dst + 16) = packh2(x.z, x.w);
            }
        }
    }
    __syncthreads();

    const uint32_t wsb = smem_u32(sm);
    const int r0 = wid * 16 + (lane >> 2);
    const int r1 = r0 + 8;
    const bool p0 = (r0 < NTOK), p1 = (r1 < NTOK);
    const float* q0 = q + base + (long long)r0 * CCH;
    const float* q1 = q + base + (long long)r1 * CCH;
    const int tq = lane & 3;
    const int cb = 2 * tq;

    // ---- S = (Qs*log2e).K^T : sacc[ntile(7)][4] ----
    float sacc[7][4];
#pragma unroll
    for (int nt = 0; nt < 7; ++nt)
#pragma unroll
        for (int e = 0; e < 4; ++e) sacc[nt][e] = 0.f;

    const uint32_t kAddrBase = wsb + ((lane & 7) + ((lane & 16) ? 8 : 0)) * STRB + ((lane & 8) ? 16 : 0);

#pragma unroll
    for (int kk = 0; kk < 2; ++kk) {
        // Q fragments: one float4 per row covers the thread's 4 fragment elements (k-permuted)
        uint32_t qh[4], ql[4];
        {
            const float4 z4 = make_float4(0.f, 0.f, 0.f, 0.f);
            int c = 16 * kk + 4 * tq;
            float4 x0 = p0 ? *(const float4*)(q0 + c) : z4;
            float4 x1 = p1 ? *(const float4*)(q1 + c) : z4;
            splith(x0.x * QSC, x0.y * QSC, qh[0], ql[0]);
            splith(x1.x * QSC, x1.y * QSC, qh[1], ql[1]);
            splith(x0.z * QSC, x0.w * QSC, qh[2], ql[2]);
            splith(x1.z * QSC, x1.w * QSC, qh[3], ql[3]);
        }
#pragma unroll
        for (int p = 0; p < 4; ++p) {
            uint32_t kh[4];
            ldsm4(kh, kAddrBase + p * (16 * STRB) + kk * 32);
#pragma unroll
            for (int nl = 0; nl < 2; ++nl) {
                int nt = 2 * p + nl;
                if (nt < 7) {
                    mma16816h(sacc[nt], qh, &kh[2 * nl]);
                    mma16816h(sacc[nt], ql, &kh[2 * nl]);
                }
            }
        }
    }

    // ---- softmax: exp2(s + bias), pad columns auto-masked by bias = -30000 ----
    float inv[2];
#pragma unroll
    for (int hh = 0; hh < 2; ++hh) {
        int i = wid * 16 + (lane >> 2) + hh * 8;
        bool vrow = (i < NTOK);
        const __half* bp = sB + (vrow ? i : 0) * BJP + cb;
        float rsum = 0.f;
#pragma unroll
        for (int nt = 0; nt < 7; ++nt) {
            float2 bb = __half22float2(*(const __half2*)(bp + 8 * nt));
            float e0 = exp2f(sacc[nt][2 * hh] + bb.x);
            float e1 = exp2f(sacc[nt][2 * hh + 1] + bb.y);
            sacc[nt][2 * hh] = e0;
            sacc[nt][2 * hh + 1] = e1;
            rsum += e0 + e1;
        }
        rsum += __shfl_xor_sync(0xffffffffu, rsum, 1);
        rsum += __shfl_xor_sync(0xffffffffu, rsum, 2);
        inv[hh] = __fdividef(1.f, rsum);
    }

    // ---- O = P.V : fp16 x fp16, single-term ----
    float oacc[4][4];
#pragma unroll
    for (int n = 0; n < 4; ++n)
#pragma unroll
        for (int e = 0; e < 4; ++e) oacc[n][e] = 0.f;

    const uint32_t vAddrBase = wsb + MATB + (lane & 15) * STRB + (lane & 16);

#pragma unroll
    for (int kc = 0; kc < 4; ++kc) {
        uint32_t vh[2][4];
#pragma unroll
        for (int np = 0; np < 2; ++np)
            ldsm4t(vh[np], vAddrBase + kc * (16 * STRB) + np * 32);
        uint32_t ah[4];
        ah[0] = packh2(sacc[2 * kc][0], sacc[2 * kc][1]);
        ah[1] = packh2(sacc[2 * kc][2], sacc[2 * kc][3]);
        if (kc < 3) {
            ah[2] = packh2(sacc[2 * kc + 1][0], sacc[2 * kc + 1][1]);
            ah[3] = packh2(sacc[2 * kc + 1][2], sacc[2 * kc + 1][3]);
        } else {
            ah[2] = ah[3] = 0u;                  // keys 56-63 are pad
        }
#pragma unroll
        for (int n = 0; n < 4; ++n)
            mma16816h(oacc[n], ah, &vh[n >> 1][2 * (n & 1)]);
    }

    // ---- epilogue: normalize + store (d-permutation -> 2 contiguous float4 per row) ----
#pragma unroll
    for (int hh = 0; hh < 2; ++hh) {
        int i = wid * 16 + (lane >> 2) + hh * 8;
        if (i < NTOK) {
            float* op = out + base + (long long)i * CCH + 8 * tq;
            float iv = inv[hh];
            float4 o1, o2;
            o1.x = oacc[0][2 * hh]     * iv;
            o1.y = oacc[0][2 * hh + 1] * iv;
            o1.z = oacc[1][2 * hh]     * iv;
            o1.w = oacc[1][2 * hh + 1] * iv;
            o2.x = oacc[2][2 * hh]     * iv;
            o2.y = oacc[2][2 * hh + 1] * iv;
            o2.z = oacc[3][2 * hh]     * iv;
            o2.w = oacc[3][2 * hh + 1] * iv;
            *(float4*)op = o1;
            *(float4*)(op + 4) = o2;
        }
    }
}

extern "C" void kernel_launch(void* const* d_in, const int* in_sizes, int n_in,
                              void* d_out, int out_size) {
    const float* q  = (const float*)d_in[0];
    const float* k  = (const float*)d_in[1];
    const float* v  = (const float*)d_in[2];
    const float* W1 = (const float*)d_in[3];
    const float* b1 = (const float*)d_in[4];
    const float* W2 = (const float*)d_in[5];
    const float* b2 = (const float*)d_in[6];
    float* out = (float*)d_out;

    const int B = in_sizes[0] / (NTOK * CCH);   // 2048
    const int nwin = B * NUM_HEADS;             // 16384

    bias_kernel<<<NUM_HEADS, 256>>>(W1, b1, W2, b2);
    attn_mma<<<nwin, 128>>>(q, k, v, out);
}

// round 16
// speedup vs baseline: 1.8732x; 1.0469x over previous
#include <cuda_runtime.h>
#include <cuda_fp16.h>
#include <cstdint>

#define NUM_HEADS 8
#define GS 7
#define NTOK 49
#define HDIM 32
#define CCH 256
#define NBIAS 169
#define HID 64
#define SCALE 0.17677669529663687f   // 32^-0.5
#define LOG2E 1.4426950408889634f
#define QSC (SCALE * LOG2E)           // fold softmax exp base conversion into Q
#define STRB 80                       // smem row stride (bytes), conflict-free for ldmatrix
#define MATB (64 * STRB)              // bytes per 64-row 16-bit matrix (5120)
#define BROW 64                       // bias row: [tq(4)][16 halfs] = 64 halfs = 128 B
#define BIASB (NTOK * BROW * 2)       // bias block bytes, fp16 (6272)

// bias table: [h][i][tq][16] fp16 (x log2e; masked cols = -30000)
__device__ __half g_biasH[NUM_HEADS * NTOK * BROW];

// ---------------- helpers ----------------
__device__ __forceinline__ uint32_t smem_u32(const void* p) {
    uint32_t a;
    asm("{ .reg .u64 t; cvta.to.shared.u64 t, %1; cvt.u32.u64 %0, t; }" : "=r"(a) : "l"(p));
    return a;
}
__device__ __forceinline__ void ldsm4(uint32_t* r, uint32_t a) {
    asm volatile("ldmatrix.sync.aligned.m8n8.x4.shared.b16 {%0,%1,%2,%3}, [%4];"
                 : "=r"(r[0]), "=r"(r[1]), "=r"(r[2]), "=r"(r[3]) : "r"(a));
}
__device__ __forceinline__ void ldsm4t(uint32_t* r, uint32_t a) {
    asm volatile("ldmatrix.sync.aligned.m8n8.x4.trans.shared.b16 {%0,%1,%2,%3}, [%4];"
                 : "=r"(r[0]), "=r"(r[1]), "=r"(r[2]), "=r"(r[3]) : "r"(a));
}
__device__ __forceinline__ void mma16816h(float* c, const uint32_t* a, const uint32_t* b) {
    asm volatile("mma.sync.aligned.m16n8k16.row.col.f32.f16.f16.f32 "
                 "{%0,%1,%2,%3}, {%4,%5,%6,%7}, {%8,%9}, {%0,%1,%2,%3};"
                 : "+f"(c[0]), "+f"(c[1]), "+f"(c[2]), "+f"(c[3])
                 : "r"(a[0]), "r"(a[1]), "r"(a[2]), "r"(a[3]), "r"(b[0]), "r"(b[1]));
}
// pack (lo,hi) floats -> f16x2 (lo in low half)
__device__ __forceinline__ uint32_t packh2(float lo, float hi) {
    uint32_t d;
    asm("cvt.rn.f16x2.f32 %0, %1, %2;" : "=r"(d) : "f"(hi), "f"(lo));
    return d;
}
// split pair into fp16 hi part + fp16 residual part
__device__ __forceinline__ void splith(float e0, float e1, uint32_t& hi, uint32_t& lo) {
    hi = packh2(e0, e1);
    float2 f = __half22float2(*(const __half2*)&hi);
    lo = packh2(e0 - f.x, e1 - f.y);
}
__device__ __forceinline__ float2 h2f(uint32_t u) {
    return __half22float2(*(const __half2*)&u);
}

// ------- bias precompute: [h][i][tq][16], fp16, x log2e, mask = -30000 -------
__global__ void bias_kernel(const float* __restrict__ W1, const float* __restrict__ b1,
                            const float* __restrict__ W2, const float* __restrict__ b2) {
    __shared__ float pos[NBIAS];
    const int h = blockIdx.x;
    const int t = threadIdx.x;
    if (t < NBIAS) {
        float bh = (float)(t / (2 * GS - 1)) - (float)(GS - 1);
        float bw = (float)(t % (2 * GS - 1)) - (float)(GS - 1);
        float acc = b2[h];
        for (int kk = 0; kk < HID; ++kk) {
            float hv = fmaxf(fmaf(bh, W1[kk], fmaf(bw, W1[HID + kk], b1[kk])), 0.0f);
            acc = fmaf(hv, W2[kk * NUM_HEADS + h], acc);
        }
        pos[t] = acc;
    }
    __syncthreads();
    for (int idx = t; idx < NTOK * BROW; idx += blockDim.x) {
        int i = idx / BROW;
        int r = idx % BROW;
        int tq = r >> 4, c2 = r & 15;
        int nt = c2 >> 1, d = c2 & 1;
        int j = 8 * nt + 2 * tq + d;
        float val = -30000.0f;                   // mask: exp2 -> 0
        if (c2 < 14 && j < NTOK) {
            int rel = (i / GS - j / GS + (GS - 1)) * (2 * GS - 1) + (i % GS - j % GS + (GS - 1));
            val = pos[rel] * LOG2E;
        }
        g_biasH[(h * NTOK + i) * BROW + r] = __float2half(val);
    }
}

// ---------------- mma attention: CTA = 1 window, 4 warps x 16 rows ----------------
// k-dim permutation: mma col (16kk + 2t + d + 8e) holds gmem col (16kk + 4t + 2e + d)
// d-dim permutation: V smem pos (2t + 8n + d) holds gmem col (8t + 2n + d)
// K: single fp16 plane; Q: fp16 hi+residual; bias: sacc init (mma accumulates on top)
__global__ __launch_bounds__(128, 8)
void attn_mma(const float* __restrict__ q, const float* __restrict__ k,
              const float* __restrict__ v, float* __restrict__ out) {
    // smem: Kf16 | Vf16 (10240) + fp16 bias block (6272)
    __shared__ unsigned char sm[2 * MATB + BIASB];
    const int tid = threadIdx.x;
    const int lane = tid & 31;
    const int wid = tid >> 5;

    const int gwid = blockIdx.x;                 // window id = (b,h)
    const int h = gwid & 7;
    const long long base = (long long)(gwid >> 3) * (NTOK * CCH) + h * HDIM;

    unsigned char* sB = sm + 2 * MATB;

    // ---- stage fp16 bias block for this head into smem (uint4, unrolled) ----
    {
        const uint4* gb = (const uint4*)(g_biasH + h * (NTOK * BROW));
        uint4* db = (uint4*)sB;
#pragma unroll
        for (int it = 0; it < 4; ++it) {
            int idx = tid + it * 128;            // 0..391
            if (idx < BIASB / 16) db[idx] = gb[idx];
        }
    }

    // ---- zero pad rows 49..63 of K and V planes ----
    {
        const float4 z4 = make_float4(0.f, 0.f, 0.f, 0.f);
#pragma unroll
        for (int it = 0; it < 2; ++it) {
            int idx = tid + it * 128;            // need 150
            if (idx < 150) {
                int m = idx / 75, rem = idx % 75;
                int row = 49 + rem / 5, c = rem % 5;
                *(float4*)(sm + m * MATB + row * STRB + c * 16) = z4;
            }
        }
    }

    // ---- stage K (fp16, k-permuted), V (fp16, d-permuted) rows 0..48 ----
    {
        const int c = tid & 7;
        const int r0w = tid >> 3;                // 0..15
        const int koff = 32 * (c >> 2) + 4 * (c & 3);
        const int voff = 4 * (c >> 1) + 32 * (c & 1);
#pragma unroll
        for (int it = 0; it < 7; ++it) {
            int row = r0w + it * 16;             // 0..111
            if (row < 98) {
                int mat = (row >= 49) ? 1 : 0;   // 0 = K, 1 = V
                int r = row - 49 * mat;
                const float* src = mat ? v : k;
                float4 x = ((const float4*)(src + base + (long long)r * CCH))[c];
                unsigned char* dst = sm + mat * MATB + r * STRB + (mat ? voff : koff);
                *(uint32_t*)dst = packh2(x.x, x.y);
                *(uint32_t*)(dst + 16) = packh2(x.z, x.w);
            }
        }
    }
    __syncthreads();

    const uint32_t wsb = smem_u32(sm);
    const int r0 = wid * 16 + (lane >> 2);
    const int r1 = r0 + 8;
    const bool p0 = (r0 < NTOK), p1 = (r1 < NTOK);
    const float* q0 = q + base + (long long)r0 * CCH;
    const float* q1 = q + base + (long long)r1 * CCH;
    const int tq = lane & 3;

    // ---- init sacc with bias (vectorized LDS.128 from reordered table) ----
    float sacc[7][4];
    {
        const uint32_t bb = wsb + 2 * MATB + tq * 32;
#pragma unroll
        for (int hh = 0; hh < 2; ++hh) {
            int i = wid * 16 + (lane >> 2) + hh * 8;
            int ic = (i < NTOK) ? i : 0;         // invalid rows masked at store
            uint4 ba = *(const uint4*)(size_t)0; // placeholder (avoid compiler warning path)
            // two 16B loads cover halfs 0..15 (nt 0..6 in first 14)
            uint4 x0, x1;
            asm volatile("ld.shared.v4.u32 {%0,%1,%2,%3}, [%4];"
                         : "=r"(x0.x), "=r"(x0.y), "=r"(x0.z), "=r"(x0.w)
                         : "r"(bb + ic * (BROW * 2)));
            asm volatile("ld.shared.v4.u32 {%0,%1,%2,%3}, [%4];"
                         : "=r"(x1.x), "=r"(x1.y), "=r"(x1.z), "=r"(x1.w)
                         : "r"(bb + ic * (BROW * 2) + 16));
            (void)ba;
            float2 f;
            f = h2f(x0.x); sacc[0][2 * hh] = f.x; sacc[0][2 * hh + 1] = f.y;
            f = h2f(x0.y); sacc[1][2 * hh] = f.x; sacc[1][2 * hh + 1] = f.y;
            f = h2f(x0.z); sacc[2][2 * hh] = f.x; sacc[2][2 * hh + 1] = f.y;
            f = h2f(x0.w); sacc[3][2 * hh] = f.x; sacc[3][2 * hh + 1] = f.y;
            f = h2f(x1.x); sacc[4][2 * hh] = f.x; sacc[4][2 * hh + 1] = f.y;
            f = h2f(x1.y); sacc[5][2 * hh] = f.x; sacc[5][2 * hh + 1] = f.y;
            f = h2f(x1.z); sacc[6][2 * hh] = f.x; sacc[6][2 * hh + 1] = f.y;
        }
    }

    // ---- S = (Qs*log2e).K^T + bias : accumulate onto bias-initialized sacc ----
    const uint32_t kAddrBase = wsb + ((lane & 7) + ((lane & 16) ? 8 : 0)) * STRB + ((lane & 8) ? 16 : 0);

#pragma unroll
    for (int kk = 0; kk < 2; ++kk) {
        uint32_t qh[4], ql[4];
        {
            const float4 z4 = make_float4(0.f, 0.f, 0.f, 0.f);
            int c = 16 * kk + 4 * tq;
            float4 x0 = p0 ? *(const float4*)(q0 + c) : z4;
            float4 x1 = p1 ? *(const float4*)(q1 + c) : z4;
            splith(x0.x * QSC, x0.y * QSC, qh[0], ql[0]);
            splith(x1.x * QSC, x1.y * QSC, qh[1], ql[1]);
            splith(x0.z * QSC, x0.w * QSC, qh[2], ql[2]);
            splith(x1.z * QSC, x1.w * QSC, qh[3], ql[3]);
        }
#pragma unroll
        for (int p = 0; p < 4; ++p) {
            uint32_t kh[4];
            ldsm4(kh, kAddrBase + p * (16 * STRB) + kk * 32);
#pragma unroll
            for (int nl = 0; nl < 2; ++nl) {
                int nt = 2 * p + nl;
                if (nt < 7) {
                    mma16816h(sacc[nt], qh, &kh[2 * nl]);
                    mma16816h(sacc[nt], ql, &kh[2 * nl]);
                }
            }
        }
    }

    // ---- softmax: exp2(sacc) — bias and mask already inside ----
    float inv[2];
#pragma unroll
    for (int hh = 0; hh < 2; ++hh) {
        float rsum = 0.f;
#pragma unroll
        for (int nt = 0; nt < 7; ++nt) {
            float e0 = exp2f(sacc[nt][2 * hh]);
            float e1 = exp2f(sacc[nt][2 * hh + 1]);
            sacc[nt][2 * hh] = e0;
            sacc[nt][2 * hh + 1] = e1;
            rsum += e0 + e1;
        }
        rsum += __shfl_xor_sync(0xffffffffu, rsum, 1);
        rsum += __shfl_xor_sync(0xffffffffu, rsum, 2);
        inv[hh] = __fdividef(1.f, rsum);
    }

    // ---- O = P.V : fp16 x fp16, single-term ----
    float oacc[4][4];
#pragma unroll
    for (int n = 0; n < 4; ++n)
#pragma unroll
        for (int e = 0; e < 4; ++e) oacc[n][e] = 0.f;

    const uint32_t vAddrBase = wsb + MATB + (lane & 15) * STRB + (lane & 16);

#pragma unroll
    for (int kc = 0; kc < 4; ++kc) {
        uint32_t vh[2][4];
#pragma unroll
        for (int np = 0; np < 2; ++np)
            ldsm4t(vh[np], vAddrBase + kc * (16 * STRB) + np * 32);
        uint32_t ah[4];
        ah[0] = packh2(sacc[2 * kc][0], sacc[2 * kc][1]);
        ah[1] = packh2(sacc[2 * kc][2], sacc[2 * kc][3]);
        if (kc < 3) {
            ah[2] = packh2(sacc[2 * kc + 1][0], sacc[2 * kc + 1][1]);
            ah[3] = packh2(sacc[2 * kc + 1][2], sacc[2 * kc + 1][3]);
        } else {
            ah[2] = ah[3] = 0u;                  // keys 56-63 are pad
        }
#pragma unroll
        for (int n = 0; n < 4; ++n)
            mma16816h(oacc[n], ah, &vh[n >> 1][2 * (n & 1)]);
    }

    // ---- epilogue: normalize + store (d-permutation -> 2 contiguous float4 per row) ----
#pragma unroll
    for (int hh = 0; hh < 2; ++hh) {
        int i = wid * 16 + (lane >> 2) + hh * 8;
        if (i < NTOK) {
            float* op = out + base + (long long)i * CCH + 8 * tq;
            float iv = inv[hh];
            float4 o1, o2;
            o1.x = oacc[0][2 * hh]     * iv;
            o1.y = oacc[0][2 * hh + 1] * iv;
            o1.z = oacc[1][2 * hh]     * iv;
            o1.w = oacc[1][2 * hh + 1] * iv;
            o2.x = oacc[2][2 * hh]     * iv;
            o2.y = oacc[2][2 * hh + 1] * iv;
            o2.z = oacc[3][2 * hh]     * iv;
            o2.w = oacc[3][2 * hh + 1] * iv;
            *(float4*)op = o1;
            *(float4*)(op + 4) = o2;
        }
    }
}

extern "C" void kernel_launch(void* const* d_in, const int* in_sizes, int n_in,
                              void* d_out, int out_size) {
    const float* q  = (const float*)d_in[0];
    const float* k  = (const float*)d_in[1];
    const float* v  = (const float*)d_in[2];
    const float* W1 = (const float*)d_in[3];
    const float* b1 = (const float*)d_in[4];
    const float* W2 = (const float*)d_in[5];
    const float* b2 = (const float*)d_in[6];
    float* out = (float*)d_out;

    const int B = in_sizes[0] / (NTOK * CCH);   // 2048
    const int nwin = B * NUM_HEADS;             // 16384

    bias_kernel<<<NUM_HEADS, 256>>>(W1, b1, W2, b2);
    attn_mma<<<nwin, 128>>>(q, k, v, out);
}